// round 1
// baseline (speedup 1.0000x reference)
#include <cuda_runtime.h>
#include <math.h>

#define N_TOK   8192
#define DMODEL  1024
#define QKVD    3072
#define NHEAD   16
#define DHEAD   64
#define NEXP    8
#define HFF     4096
#define TSEQ    1024
#define BATCH   8
#define NLAYER  2
#define CAP     17408   // 16384 assignments + 8*128 alignment pad

// ---------------- device scratch (static, no runtime alloc) ----------------
__device__ float g_x[N_TOK*DMODEL];
__device__ float g_qkv[(size_t)N_TOK*QKVD];
__device__ float g_h[N_TOK*DMODEL];
__device__ float g_tmp[N_TOK*DMODEL];
__device__ float g_moe[N_TOK*DMODEL];
__device__ float g_h1[(size_t)CAP*HFF];
__device__ float g_probs[N_TOK*NEXP];
__device__ int   g_tki[N_TOK*2];
__device__ float g_tkw[N_TOK*2];
__device__ int   g_counts[NEXP];
__device__ int   g_cursor[NEXP];
__device__ int   g_off[NEXP+1];
__device__ int   g_atok[CAP];
__device__ float g_aw[CAP];
__device__ float g_Pc[NEXP];
__device__ float g_lb;

// ---------------- reductions (fixed tree -> deterministic) ----------------
__device__ __forceinline__ float warpRedSum(float v){
#pragma unroll
    for (int o = 16; o; o >>= 1) v += __shfl_xor_sync(0xffffffffu, v, o);
    return v;
}
__device__ __forceinline__ float warpRedMax(float v){
#pragma unroll
    for (int o = 16; o; o >>= 1) v = fmaxf(v, __shfl_xor_sync(0xffffffffu, v, o));
    return v;
}
__device__ float blockRedSum(float v, float* red){
    int lane = threadIdx.x & 31, w = threadIdx.x >> 5, nw = blockDim.x >> 5;
    __syncthreads();
    v = warpRedSum(v);
    if (lane == 0) red[w] = v;
    __syncthreads();
    if (w == 0){
        float x = (lane < nw) ? red[lane] : 0.f;
        x = warpRedSum(x);
        if (lane == 0) red[0] = x;
    }
    __syncthreads();
    return red[0];
}
__device__ float blockRedMax(float v, float* red){
    int lane = threadIdx.x & 31, w = threadIdx.x >> 5, nw = blockDim.x >> 5;
    __syncthreads();
    v = warpRedMax(v);
    if (lane == 0) red[w] = v;
    __syncthreads();
    if (w == 0){
        float x = (lane < nw) ? red[lane] : -3.0e38f;
        x = warpRedMax(x);
        if (lane == 0) red[0] = x;
    }
    __syncthreads();
    return red[0];
}

// ---------------- embedding + positional ----------------
__global__ void embed_kernel(const int* __restrict__ ids,
                             const float* __restrict__ emb,
                             const float* __restrict__ pos){
    int n = blockIdx.x, tid = threadIdx.x;           // 256 threads
    int t = n & (TSEQ - 1);
    int id = ids[n];
#pragma unroll
    for (int i = 0; i < 4; i++){
        int d = tid + i * 256;
        g_x[(size_t)n*DMODEL + d] = emb[(size_t)id*DMODEL + d] + pos[(size_t)t*DMODEL + d];
    }
}

// ---------------- generic 128x128x8 SGEMM, 4 fused variants ----------------
// MODE 0: g_qkv = g_x @ B + bias                (N=3072, K=1024)
// MODE 1: g_tmp = g_h @ B + bias                (N=1024, K=1024)
// MODE 2: g_h1  = relu(gather(g_x) @ B[e]+b[e]) (N=4096, K=1024) per-expert
// MODE 3: g_moe += w * (g_h1 @ B[e] + b[e])     (N=1024, K=4096) scatter
template<int MODE>
__global__ void __launch_bounds__(256, 2)
sgemm_kernel(const float* __restrict__ Bmat,
             const float* __restrict__ biasB,
             int N, int K)
{
    int bn = blockIdx.x * 128;
    int bm = blockIdx.y * 128;
    int tid = threadIdx.x;

    int e = 0, rowLimit = 0;
    if (MODE == 2 || MODE == 3){
        if (bm >= g_off[NEXP]) return;
#pragma unroll
        for (int i = 1; i < NEXP; i++) if (bm >= g_off[i]) e = i;
        rowLimit = g_off[e] + g_counts[e];
        Bmat  += (size_t)e * K * N;
        biasB += (size_t)e * N;
    }

    __shared__ __align__(16) float As[8][128];
    __shared__ __align__(16) float Bs[8][128];

    int arow = tid >> 1;
    int k4   = (tid & 1) * 4;
    const float* Arow;
    if      (MODE == 0) Arow = &g_x [(size_t)(bm + arow) * DMODEL];
    else if (MODE == 1) Arow = &g_h [(size_t)(bm + arow) * DMODEL];
    else if (MODE == 2) Arow = &g_x [(size_t)g_atok[bm + arow] * DMODEL];
    else                Arow = &g_h1[(size_t)(bm + arow) * HFF];

    int brow  = tid >> 5;
    int bcolL = (tid & 31) * 4;

    int warp = tid >> 5, lane = tid & 31;
    int ar0 = (warp >> 1) * 32 + (lane >> 3) * 4;   // 4 row-groups of 4 + offset 16
    int bc0 = (warp & 1) * 64 + (lane & 7) * 4;     // 8 col-groups of 4 + offset 32

    float acc[8][8];
#pragma unroll
    for (int i = 0; i < 8; i++)
#pragma unroll
        for (int j = 0; j < 8; j++) acc[i][j] = 0.f;

    float4 pa = *(const float4*)(Arow + k4);
    float4 pb = *(const float4*)(Bmat + (size_t)brow * N + bn + bcolL);

    for (int k0 = 0; k0 < K; k0 += 8){
        As[k4+0][arow] = pa.x; As[k4+1][arow] = pa.y;
        As[k4+2][arow] = pa.z; As[k4+3][arow] = pa.w;
        *(float4*)&Bs[brow][bcolL] = pb;
        __syncthreads();
        if (k0 + 8 < K){
            pa = *(const float4*)(Arow + k0 + 8 + k4);
            pb = *(const float4*)(Bmat + (size_t)(k0 + 8 + brow) * N + bn + bcolL);
        }
#pragma unroll
        for (int kk = 0; kk < 8; kk++){
            float4 a0 = *(const float4*)&As[kk][ar0];
            float4 a1 = *(const float4*)&As[kk][ar0 + 16];
            float4 b0 = *(const float4*)&Bs[kk][bc0];
            float4 b1 = *(const float4*)&Bs[kk][bc0 + 32];
            float av[8] = {a0.x,a0.y,a0.z,a0.w,a1.x,a1.y,a1.z,a1.w};
            float bv[8] = {b0.x,b0.y,b0.z,b0.w,b1.x,b1.y,b1.z,b1.w};
#pragma unroll
            for (int i = 0; i < 8; i++)
#pragma unroll
                for (int j = 0; j < 8; j++) acc[i][j] += av[i] * bv[j];
        }
        __syncthreads();
    }

#pragma unroll
    for (int i = 0; i < 8; i++){
        int r = bm + ar0 + ((i < 4) ? i : (12 + i));   // +16 offset for second group
        if (MODE == 3){
            if (r >= rowLimit) continue;               // pad rows: discard
            int   tok = g_atok[r];
            float w   = g_aw[r];
#pragma unroll
            for (int j = 0; j < 8; j++){
                int c = bn + bc0 + ((j < 4) ? j : (28 + j));
                atomicAdd(&g_moe[(size_t)tok*DMODEL + c], w * (acc[i][j] + biasB[c]));
            }
        } else {
#pragma unroll
            for (int j = 0; j < 8; j++){
                int c = bn + bc0 + ((j < 4) ? j : (28 + j));
                float v = acc[i][j] + biasB[c];
                if      (MODE == 0) g_qkv[(size_t)r*QKVD  + c] = v;
                else if (MODE == 1) g_tmp[(size_t)r*DMODEL + c] = v;
                else                g_h1 [(size_t)r*HFF    + c] = fmaxf(v, 0.f);
            }
        }
    }
}

// ---------------- causal attention: block per (t, h, b), 2-pass softmax ----
__global__ void attn_kernel(const int* __restrict__ amask){
    int t = blockIdx.x, h = blockIdx.y, b = blockIdx.z;
    int tid = threadIdx.x;                       // 128 threads
    __shared__ float qs[64];
    __shared__ float pr[TSEQ];
    __shared__ float red[32];
    __shared__ float outs[64];
    int n = b * TSEQ + t;
    if (tid < 64) qs[tid] = g_qkv[(size_t)n*QKVD + h*DHEAD + tid];
    __syncthreads();

    float lmax = -3.0e38f;
    for (int s = tid; s <= t; s += 128){
        const float* kr = &g_qkv[(size_t)(b*TSEQ + s)*QKVD + DMODEL + h*DHEAD];
        float dot = 0.f;
#pragma unroll
        for (int d = 0; d < 64; d += 4){
            float4 kv = *(const float4*)(kr + d);
            dot += qs[d]*kv.x + qs[d+1]*kv.y + qs[d+2]*kv.z + qs[d+3]*kv.w;
        }
        float sc = dot * 0.125f;                 // 1/sqrt(64)
        if (amask[b*TSEQ + s] == 0) sc = -1e9f;
        pr[s] = sc;
        lmax = fmaxf(lmax, sc);
    }
    float mx = blockRedMax(lmax, red);
    float ls = 0.f;
    for (int s = tid; s <= t; s += 128){
        float p = __expf(pr[s] - mx);
        pr[s] = p; ls += p;
    }
    float sum = blockRedSum(ls, red);
    float inv = 1.f / sum;

    int d = tid & 63, half = tid >> 6;
    float acc = 0.f;
    for (int s = half; s <= t; s += 2)
        acc += pr[s] * g_qkv[(size_t)(b*TSEQ + s)*QKVD + 2*DMODEL + h*DHEAD + d];
    if (half == 0) outs[d] = acc;
    __syncthreads();
    if (half == 1) outs[d] += acc;
    __syncthreads();
    if (tid < 64) g_h[(size_t)n*DMODEL + h*DHEAD + tid] = outs[tid] * inv;
}

// ---------------- residual add + LayerNorm (in-place on g_x) ----------------
__global__ void add_ln_kernel(int which, const float* __restrict__ g,
                              const float* __restrict__ bta){
    int n = blockIdx.x, tid = threadIdx.x;       // 256 threads
    __shared__ float red[32];
    const float* addsrc = which ? g_moe : g_tmp;
    float v[4];
    float s = 0.f;
#pragma unroll
    for (int i = 0; i < 4; i++){
        int d = tid + i*256;
        v[i] = g_x[(size_t)n*DMODEL + d] + addsrc[(size_t)n*DMODEL + d];
        s += v[i];
    }
    float mean = blockRedSum(s, red) * (1.f/DMODEL);
    float vs = 0.f;
#pragma unroll
    for (int i = 0; i < 4; i++){ float dd = v[i] - mean; vs += dd*dd; }
    float var = blockRedSum(vs, red) * (1.f/DMODEL);
    float r = rsqrtf(var + 1e-5f);
#pragma unroll
    for (int i = 0; i < 4; i++){
        int d = tid + i*256;
        g_x[(size_t)n*DMODEL + d] = (v[i] - mean)*r*g[d] + bta[d];
    }
}

// ---------------- router: gate GEMV + softmax + top-2 ----------------
__global__ void gate_kernel(const float* __restrict__ W, const float* __restrict__ bb){
    int n = blockIdx.x, tid = threadIdx.x;       // 128 threads
    __shared__ float sred[NEXP][128];
    float acc[NEXP];
#pragma unroll
    for (int e = 0; e < NEXP; e++) acc[e] = 0.f;
    const float* xr = &g_x[(size_t)n*DMODEL];
    for (int d = tid; d < DMODEL; d += 128){
        float xv = xr[d];
#pragma unroll
        for (int e = 0; e < NEXP; e++) acc[e] += xv * W[d*NEXP + e];
    }
#pragma unroll
    for (int e = 0; e < NEXP; e++) sred[e][tid] = acc[e];
    __syncthreads();
    for (int s = 64; s > 0; s >>= 1){
        if (tid < s){
#pragma unroll
            for (int e = 0; e < NEXP; e++) sred[e][tid] += sred[e][tid + s];
        }
        __syncthreads();
    }
    if (tid == 0){
        float lg[NEXP], mx = -3e38f;
#pragma unroll
        for (int e = 0; e < NEXP; e++){ lg[e] = sred[e][0] + bb[e]; mx = fmaxf(mx, lg[e]); }
        float s = 0.f, p[NEXP];
#pragma unroll
        for (int e = 0; e < NEXP; e++){ p[e] = __expf(lg[e] - mx); s += p[e]; }
        float invs = 1.f / s;
#pragma unroll
        for (int e = 0; e < NEXP; e++){ p[e] *= invs; g_probs[n*NEXP + e] = p[e]; }
        int i1 = 0;
#pragma unroll
        for (int e = 1; e < NEXP; e++) if (p[e] > p[i1]) i1 = e;
        int i2 = (i1 == 0) ? 1 : 0;
#pragma unroll
        for (int e = 0; e < NEXP; e++) if (e != i1 && p[e] > p[i2]) i2 = e;
        float sw = p[i1] + p[i2];
        g_tki[n*2]   = i1; g_tki[n*2+1] = i2;
        g_tkw[n*2]   = p[i1] / sw;
        g_tkw[n*2+1] = p[i2] / sw;
        atomicAdd(&g_counts[i1], 1);
        atomicAdd(&g_counts[i2], 1);
    }
}

// ---------------- per-layer reset ----------------
__global__ void reset_kernel(){
    int i = blockIdx.x * blockDim.x + threadIdx.x;
    if (i < N_TOK*DMODEL) g_moe[i] = 0.f;
    if (i < CAP){ g_atok[i] = 0; g_aw[i] = 0.f; }
    if (i < NEXP){ g_counts[i] = 0; g_cursor[i] = 0; }
}

// 128-aligned exclusive scan over expert counts (E=8, single thread)
__global__ void scan_kernel(){
    if (threadIdx.x == 0){
        int o = 0;
        for (int e = 0; e < NEXP; e++){
            g_off[e] = o;
            o += (g_counts[e] + 127) & ~127;
        }
        g_off[NEXP] = o;
    }
}

__global__ void scatter_kernel(){
    int n = blockIdx.x * blockDim.x + threadIdx.x;
    if (n >= N_TOK) return;
#pragma unroll
    for (int k = 0; k < 2; k++){
        int e = g_tki[n*2 + k];
        int pos = atomicAdd(&g_cursor[e], 1);
        int slot = g_off[e] + pos;
        g_atok[slot] = n;
        g_aw[slot]   = g_tkw[n*2 + k];
    }
}

// ---------------- load-balance loss (deterministic reductions) ----------------
__global__ void lb_part_kernel(){
    int e = blockIdx.x, tid = threadIdx.x;       // 8 blocks x 256
    __shared__ float red[32];
    float s = 0.f;
    for (int n = tid; n < N_TOK; n += 256) s += g_probs[n*NEXP + e];
    float tot = blockRedSum(s, red);
    if (tid == 0)
        g_Pc[e] = (float)NEXP * ((float)g_counts[e] / (float)N_TOK) * (tot / (float)N_TOK);
}
__global__ void lb_acc_kernel(){
    if (threadIdx.x == 0){
        float s = 0.f;
        for (int e = 0; e < NEXP; e++) s += g_Pc[e];
        g_lb += s;
    }
}
__global__ void init_kernel(){ g_lb = 0.f; }

// ---------------- output ----------------
__global__ void finalize_kernel(float* __restrict__ out, int out_size){
    int i = blockIdx.x * blockDim.x + threadIdx.x;
    if (i >= out_size) return;
    if (i < N_TOK*DMODEL) out[i] = g_x[i];
    else                  out[i] = g_lb;   // scalar lb_loss appended
}

// ---------------- host orchestration ----------------
extern "C" void kernel_launch(void* const* d_in, const int* in_sizes, int n_in,
                              void* d_out, int out_size)
{
    const int*   ids  = (const int*)  d_in[0];
    const int*   am   = (const int*)  d_in[1];
    const float* emb  = (const float*)d_in[2];
    const float* pos  = (const float*)d_in[3];
    const float* Wqkv = (const float*)d_in[4];
    const float* bqkv = (const float*)d_in[5];
    const float* Wo   = (const float*)d_in[6];
    const float* bo   = (const float*)d_in[7];
    const float* ln1g = (const float*)d_in[8];
    const float* ln1b = (const float*)d_in[9];
    const float* ln2g = (const float*)d_in[10];
    const float* ln2b = (const float*)d_in[11];
    const float* gW   = (const float*)d_in[12];
    const float* gb   = (const float*)d_in[13];
    const float* W1   = (const float*)d_in[14];
    const float* b1   = (const float*)d_in[15];
    const float* W2   = (const float*)d_in[16];
    const float* b2   = (const float*)d_in[17];

    init_kernel<<<1, 1>>>();
    embed_kernel<<<N_TOK, 256>>>(ids, emb, pos);

    for (int l = 0; l < NLAYER; l++){
        // QKV projection
        sgemm_kernel<0><<<dim3(QKVD/128, N_TOK/128), 256>>>(
            Wqkv + (size_t)l*DMODEL*QKVD, bqkv + (size_t)l*QKVD, QKVD, DMODEL);
        // causal MHA
        attn_kernel<<<dim3(TSEQ, NHEAD, BATCH), 128>>>(am);
        // output projection
        sgemm_kernel<1><<<dim3(DMODEL/128, N_TOK/128), 256>>>(
            Wo + (size_t)l*DMODEL*DMODEL, bo + (size_t)l*DMODEL, DMODEL, DMODEL);
        // x = LN(x + attn_out)
        add_ln_kernel<<<N_TOK, 256>>>(0, ln1g + (size_t)l*DMODEL, ln1b + (size_t)l*DMODEL);

        // MoE routing
        reset_kernel<<<(N_TOK*DMODEL + 255)/256, 256>>>();
        gate_kernel<<<N_TOK, 128>>>(gW + (size_t)l*DMODEL*NEXP, gb + (size_t)l*NEXP);
        scan_kernel<<<1, 1>>>();
        scatter_kernel<<<(N_TOK + 255)/256, 256>>>();

        // expert FFN (sparse: only routed tokens)
        sgemm_kernel<2><<<dim3(HFF/128, CAP/128), 256>>>(
            W1 + (size_t)l*NEXP*DMODEL*HFF, b1 + (size_t)l*NEXP*HFF, HFF, DMODEL);
        sgemm_kernel<3><<<dim3(DMODEL/128, CAP/128), 256>>>(
            W2 + (size_t)l*NEXP*HFF*DMODEL, b2 + (size_t)l*NEXP*DMODEL, DMODEL, HFF);

        // load-balance loss
        lb_part_kernel<<<NEXP, 256>>>();
        lb_acc_kernel<<<1, 1>>>();

        // x = LN(x + moe_out)
        add_ln_kernel<<<N_TOK, 256>>>(1, ln2g + (size_t)l*DMODEL, ln2b + (size_t)l*DMODEL);
    }

    int total = out_size > N_TOK*DMODEL ? out_size : N_TOK*DMODEL;
    finalize_kernel<<<(total + 255)/256, 256>>>((float*)d_out, out_size);
}

// round 3
// speedup vs baseline: 1.2569x; 1.2569x over previous
#include <cuda_runtime.h>
#include <math.h>

#define N_TOK   8192
#define DMODEL  1024
#define QKVD    3072
#define NHEAD   16
#define DHEAD   64
#define NEXP    8
#define HFF     4096
#define TSEQ    1024
#define BATCH   8
#define NLAYER  2
#define CAP     17408   // 16384 assignments + 8*128 alignment pad

// ---------------- device scratch ----------------
__device__ float g_x[N_TOK*DMODEL];
__device__ float g_qkv[(size_t)N_TOK*QKVD];
__device__ float g_h[N_TOK*DMODEL];
__device__ float g_tmp[N_TOK*DMODEL];
__device__ float g_moe[N_TOK*DMODEL];
__device__ float g_h1[(size_t)CAP*HFF];
__device__ float g_probs[N_TOK*NEXP];
__device__ int   g_tki[N_TOK*2];
__device__ float g_tkw[N_TOK*2];
__device__ int   g_counts[NEXP];
__device__ int   g_cursor[NEXP];
__device__ int   g_off[NEXP+1];
__device__ int   g_atok[CAP];
__device__ float g_aw[CAP];
__device__ float g_Pc[NEXP];
__device__ float g_lb;

// ---------------- reductions ----------------
__device__ __forceinline__ float warpRedSum(float v){
#pragma unroll
    for (int o = 16; o; o >>= 1) v += __shfl_xor_sync(0xffffffffu, v, o);
    return v;
}
__device__ __forceinline__ float warpRedMax(float v){
#pragma unroll
    for (int o = 16; o; o >>= 1) v = fmaxf(v, __shfl_xor_sync(0xffffffffu, v, o));
    return v;
}
__device__ float blockRedSum(float v, float* red){
    int lane = threadIdx.x & 31, w = threadIdx.x >> 5, nw = blockDim.x >> 5;
    __syncthreads();
    v = warpRedSum(v);
    if (lane == 0) red[w] = v;
    __syncthreads();
    if (w == 0){
        float x = (lane < nw) ? red[lane] : 0.f;
        x = warpRedSum(x);
        if (lane == 0) red[0] = x;
    }
    __syncthreads();
    return red[0];
}

// ---------------- tf32 helpers ----------------
__device__ __forceinline__ float f2tf(float x){
    unsigned u; asm("cvt.rna.tf32.f32 %0, %1;" : "=r"(u) : "f"(x));
    return __uint_as_float(u);
}
// hi/lo split: hi = tf32(x), lo = tf32(x - hi). hi+lo carries ~22 mantissa bits.
__device__ __forceinline__ float2 split_tf(float x){
    float hi = f2tf(x);
    float lo = f2tf(x - hi);
    return make_float2(hi, lo);
}
__device__ __forceinline__ void mma_tf32(float c[4], const unsigned a[4], const unsigned b[2]){
    asm volatile("mma.sync.aligned.m16n8k8.row.col.f32.tf32.tf32.f32 "
        "{%0,%1,%2,%3}, {%4,%5,%6,%7}, {%8,%9}, {%0,%1,%2,%3};"
        : "+f"(c[0]), "+f"(c[1]), "+f"(c[2]), "+f"(c[3])
        : "r"(a[0]), "r"(a[1]), "r"(a[2]), "r"(a[3]), "r"(b[0]), "r"(b[1]));
}

// ---------------- embedding + positional ----------------
__global__ void embed_kernel(const int* __restrict__ ids,
                             const float* __restrict__ emb,
                             const float* __restrict__ pos){
    int n = blockIdx.x, tid = threadIdx.x;
    int t = n & (TSEQ - 1);
    int id = ids[n];
#pragma unroll
    for (int i = 0; i < 4; i++){
        int d = tid + i * 256;
        g_x[(size_t)n*DMODEL + d] = emb[(size_t)id*DMODEL + d] + pos[(size_t)t*DMODEL + d];
    }
}

// ------------- 3xTF32 tensor-core GEMM, 128x128 tile, BK=16 -------------
// MODE 0: g_qkv = g_x @ B + bias                (N=3072, K=1024)
// MODE 1: g_tmp = g_h @ B + bias                (N=1024, K=1024)
// MODE 2: g_h1  = relu(gather(g_x) @ B[e]+b[e]) (N=4096, K=1024) per-expert
// MODE 3: g_moe += w * (g_h1 @ B[e] + b[e])     (N=1024, K=4096) scatter
template<int MODE>
__global__ void __launch_bounds__(256)
mma_gemm(const float* __restrict__ Bmat, const float* __restrict__ biasB,
         int N, int K)
{
    int bn = blockIdx.x * 128;
    int bm = blockIdx.y * 128;
    int tid  = threadIdx.x;
    int warp = tid >> 5, lane = tid & 31;
    int wm = warp >> 1, wn = warp & 1;

    int e = 0, rowLimit = 0;
    if (MODE == 2 || MODE == 3){
        if (bm >= g_off[NEXP]) return;
#pragma unroll
        for (int i = 1; i < NEXP; i++) if (bm >= g_off[i]) e = i;
        rowLimit = g_off[e] + g_counts[e];
        Bmat  += (size_t)e * K * N;
        biasB += (size_t)e * N;
    }

    // (hi, lo) interleaved as float2 -> one 64-bit LDS per fragment element
    __shared__ __align__(16) float2 As[128][21];   // [m][k], 16 used, pad 21
    __shared__ __align__(16) float2 Bs[16][132];   // [k][n], pad 132

    // global-load mapping
    int r0 = tid >> 2, r1 = r0 + 64;
    int k4 = (tid & 3) * 4;
    int kb0 = tid >> 5, kb1 = kb0 + 8;
    int cb  = (tid & 31) * 4;

    const float *Ap0, *Ap1;
    if      (MODE == 0){ Ap0 = &g_x [(size_t)(bm + r0) * DMODEL]; Ap1 = &g_x [(size_t)(bm + r1) * DMODEL]; }
    else if (MODE == 1){ Ap0 = &g_h [(size_t)(bm + r0) * DMODEL]; Ap1 = &g_h [(size_t)(bm + r1) * DMODEL]; }
    else if (MODE == 2){ Ap0 = &g_x [(size_t)g_atok[bm + r0] * DMODEL]; Ap1 = &g_x [(size_t)g_atok[bm + r1] * DMODEL]; }
    else               { Ap0 = &g_h1[(size_t)(bm + r0) * HFF];    Ap1 = &g_h1[(size_t)(bm + r1) * HFF]; }

    const float* Bp0 = Bmat + (size_t)kb0 * N + bn + cb;
    const float* Bp1 = Bmat + (size_t)kb1 * N + bn + cb;

    float acc[2][8][4];
#pragma unroll
    for (int mt = 0; mt < 2; mt++)
#pragma unroll
        for (int nt = 0; nt < 8; nt++)
#pragma unroll
            for (int i = 0; i < 4; i++) acc[mt][nt][i] = 0.f;

    float4 pa0 = *(const float4*)(Ap0 + k4);
    float4 pa1 = *(const float4*)(Ap1 + k4);
    float4 pb0 = *(const float4*)Bp0;
    float4 pb1 = *(const float4*)Bp1;

    int rql = lane >> 2, rqm = lane & 3;   // row-in-quad / k-in-quad

    for (int k0 = 0; k0 < K; k0 += 16){
        As[r0][k4+0] = split_tf(pa0.x); As[r0][k4+1] = split_tf(pa0.y);
        As[r0][k4+2] = split_tf(pa0.z); As[r0][k4+3] = split_tf(pa0.w);
        As[r1][k4+0] = split_tf(pa1.x); As[r1][k4+1] = split_tf(pa1.y);
        As[r1][k4+2] = split_tf(pa1.z); As[r1][k4+3] = split_tf(pa1.w);
        Bs[kb0][cb+0] = split_tf(pb0.x); Bs[kb0][cb+1] = split_tf(pb0.y);
        Bs[kb0][cb+2] = split_tf(pb0.z); Bs[kb0][cb+3] = split_tf(pb0.w);
        Bs[kb1][cb+0] = split_tf(pb1.x); Bs[kb1][cb+1] = split_tf(pb1.y);
        Bs[kb1][cb+2] = split_tf(pb1.z); Bs[kb1][cb+3] = split_tf(pb1.w);
        __syncthreads();
        if (k0 + 16 < K){
            pa0 = *(const float4*)(Ap0 + k0 + 16 + k4);
            pa1 = *(const float4*)(Ap1 + k0 + 16 + k4);
            pb0 = *(const float4*)(Bp0 + (size_t)16 * N);
            pb1 = *(const float4*)(Bp1 + (size_t)16 * N);
            Bp0 += (size_t)16 * N; Bp1 += (size_t)16 * N;
        }
#pragma unroll
        for (int kk = 0; kk < 16; kk += 8){
            unsigned ah[2][4], al[2][4];
#pragma unroll
            for (int mt = 0; mt < 2; mt++){
                int r = wm*32 + mt*16 + rql;
                float2 f0 = As[r  ][kk + rqm];
                float2 f1 = As[r+8][kk + rqm];
                float2 f2 = As[r  ][kk + 4 + rqm];
                float2 f3 = As[r+8][kk + 4 + rqm];
                ah[mt][0] = __float_as_uint(f0.x); al[mt][0] = __float_as_uint(f0.y);
                ah[mt][1] = __float_as_uint(f1.x); al[mt][1] = __float_as_uint(f1.y);
                ah[mt][2] = __float_as_uint(f2.x); al[mt][2] = __float_as_uint(f2.y);
                ah[mt][3] = __float_as_uint(f3.x); al[mt][3] = __float_as_uint(f3.y);
            }
            unsigned bh[8][2], bl[8][2];
#pragma unroll
            for (int nt = 0; nt < 8; nt++){
                int c = wn*64 + nt*8 + rql;
                float2 f0 = Bs[kk + rqm    ][c];
                float2 f1 = Bs[kk + 4 + rqm][c];
                bh[nt][0] = __float_as_uint(f0.x); bl[nt][0] = __float_as_uint(f0.y);
                bh[nt][1] = __float_as_uint(f1.x); bl[nt][1] = __float_as_uint(f1.y);
            }
#pragma unroll
            for (int mt = 0; mt < 2; mt++)
#pragma unroll
                for (int nt = 0; nt < 8; nt++){
                    mma_tf32(acc[mt][nt], ah[mt], bh[nt]);   // hi*hi
                    mma_tf32(acc[mt][nt], ah[mt], bl[nt]);   // hi*lo
                    mma_tf32(acc[mt][nt], al[mt], bh[nt]);   // lo*hi
                }
        }
        __syncthreads();
    }

    // epilogue. fragment: c0=(r,c) c1=(r,c+1) c2=(r+8,c) c3=(r+8,c+1)
    int c_lo = 2 * rqm;
#pragma unroll
    for (int mt = 0; mt < 2; mt++){
        int grA = bm + wm*32 + mt*16 + rql;
        int grB = grA + 8;
        if (MODE == 3){
            bool okA = grA < rowLimit, okB = grB < rowLimit;
            int   tokA = okA ? g_atok[grA] : 0;  float wA = okA ? g_aw[grA] : 0.f;
            int   tokB = okB ? g_atok[grB] : 0;  float wB = okB ? g_aw[grB] : 0.f;
#pragma unroll
            for (int nt = 0; nt < 8; nt++){
                int gc = bn + wn*64 + nt*8 + c_lo;
                float b0 = biasB[gc], b1 = biasB[gc+1];
                if (okA){
                    atomicAdd(&g_moe[(size_t)tokA*DMODEL + gc    ], wA*(acc[mt][nt][0] + b0));
                    atomicAdd(&g_moe[(size_t)tokA*DMODEL + gc + 1], wA*(acc[mt][nt][1] + b1));
                }
                if (okB){
                    atomicAdd(&g_moe[(size_t)tokB*DMODEL + gc    ], wB*(acc[mt][nt][2] + b0));
                    atomicAdd(&g_moe[(size_t)tokB*DMODEL + gc + 1], wB*(acc[mt][nt][3] + b1));
                }
            }
        } else {
#pragma unroll
            for (int nt = 0; nt < 8; nt++){
                int gc = bn + wn*64 + nt*8 + c_lo;
                float b0 = biasB[gc], b1 = biasB[gc+1];
                float v0 = acc[mt][nt][0] + b0, v1 = acc[mt][nt][1] + b1;
                float v2 = acc[mt][nt][2] + b0, v3 = acc[mt][nt][3] + b1;
                if (MODE == 0){
                    g_qkv[(size_t)grA*QKVD + gc] = v0; g_qkv[(size_t)grA*QKVD + gc+1] = v1;
                    g_qkv[(size_t)grB*QKVD + gc] = v2; g_qkv[(size_t)grB*QKVD + gc+1] = v3;
                } else if (MODE == 1){
                    g_tmp[(size_t)grA*DMODEL + gc] = v0; g_tmp[(size_t)grA*DMODEL + gc+1] = v1;
                    g_tmp[(size_t)grB*DMODEL + gc] = v2; g_tmp[(size_t)grB*DMODEL + gc+1] = v3;
                } else {
                    g_h1[(size_t)grA*HFF + gc]   = fmaxf(v0, 0.f);
                    g_h1[(size_t)grA*HFF + gc+1] = fmaxf(v1, 0.f);
                    g_h1[(size_t)grB*HFF + gc]   = fmaxf(v2, 0.f);
                    g_h1[(size_t)grB*HFF + gc+1] = fmaxf(v3, 0.f);
                }
            }
        }
    }
}

// ---------------- flash attention: 16 queries x 64-key tiles ----------------
// grid (T/16, NHEAD, BATCH), block 256 (8 warps, 2 queries/warp)
__global__ void __launch_bounds__(256)
attn_kernel(const int* __restrict__ amask){
    int qt = blockIdx.x, h = blockIdx.y, b = blockIdx.z;
    int tid = threadIdx.x, warp = tid >> 5, lane = tid & 31;
    int qbase = qt * 16;

    __shared__ __align__(16) float Qs[16][68];
    __shared__ __align__(16) float Ks[64][68];
    __shared__ __align__(16) float Vs[64][68];
    __shared__ __align__(16) float Ps[8][2][68];

    // load Q (scaled by 1/sqrt(dh))
    {
        int q = tid >> 4, d4 = (tid & 15) * 4;
        const float* src = &g_qkv[(size_t)(b*TSEQ + qbase + q)*QKVD + h*DHEAD + d4];
        float4 v = *(const float4*)src;
        Qs[q][d4] = v.x*0.125f; Qs[q][d4+1] = v.y*0.125f;
        Qs[q][d4+2] = v.z*0.125f; Qs[q][d4+3] = v.w*0.125f;
    }

    int qg0 = qbase + warp*2, qg1 = qg0 + 1;
    float m0 = -3.0e38f, m1 = -3.0e38f;
    float l0 = 0.f, l1 = 0.f;
    float o00 = 0.f, o01 = 0.f, o10 = 0.f, o11 = 0.f;

    int ntiles = (qbase + 15) / 64 + 1;
    for (int tile = 0; tile < ntiles; tile++){
        int j0 = tile * 64;
        __syncthreads();
#pragma unroll
        for (int p = 0; p < 4; p++){
            int idx = tid + p*256;
            int row = idx >> 4, d4 = (idx & 15)*4;
            size_t base = (size_t)(b*TSEQ + j0 + row)*QKVD + h*DHEAD + d4;
            *(float4*)&Ks[row][d4] = *(const float4*)&g_qkv[base + DMODEL];
            *(float4*)&Vs[row][d4] = *(const float4*)&g_qkv[base + 2*DMODEL];
        }
        __syncthreads();

        float s00=0.f, s01=0.f, s10=0.f, s11=0.f;
#pragma unroll
        for (int d = 0; d < 64; d += 4){
            float4 ka = *(const float4*)&Ks[lane][d];
            float4 kb = *(const float4*)&Ks[lane+32][d];
            float4 qa = *(const float4*)&Qs[warp*2][d];
            float4 qb = *(const float4*)&Qs[warp*2+1][d];
            s00 += qa.x*ka.x + qa.y*ka.y + qa.z*ka.z + qa.w*ka.w;
            s01 += qa.x*kb.x + qa.y*kb.y + qa.z*kb.z + qa.w*kb.w;
            s10 += qb.x*ka.x + qb.y*ka.y + qb.z*ka.z + qb.w*ka.w;
            s11 += qb.x*kb.x + qb.y*kb.y + qb.z*kb.z + qb.w*kb.w;
        }
        int j1 = j0 + lane, j2 = j0 + lane + 32;
        int am1 = amask[b*TSEQ + j1], am2 = amask[b*TSEQ + j2];
        if (j1 > qg0 || !am1) s00 = -1e9f;
        if (j2 > qg0 || !am2) s01 = -1e9f;
        if (j1 > qg1 || !am1) s10 = -1e9f;
        if (j2 > qg1 || !am2) s11 = -1e9f;

        {
            float tm = warpRedMax(fmaxf(s00, s01));
            float mn = fmaxf(m0, tm);
            float sc = __expf(m0 - mn);
            float pA = __expf(s00 - mn), pB = __expf(s01 - mn);
            l0 = l0*sc + warpRedSum(pA + pB);
            o00 *= sc; o01 *= sc; m0 = mn;
            Ps[warp][0][lane] = pA; Ps[warp][0][lane+32] = pB;
        }
        {
            float tm = warpRedMax(fmaxf(s10, s11));
            float mn = fmaxf(m1, tm);
            float sc = __expf(m1 - mn);
            float pA = __expf(s10 - mn), pB = __expf(s11 - mn);
            l1 = l1*sc + warpRedSum(pA + pB);
            o10 *= sc; o11 *= sc; m1 = mn;
            Ps[warp][1][lane] = pA; Ps[warp][1][lane+32] = pB;
        }
        __syncwarp();

#pragma unroll 4
        for (int j = 0; j < 64; j += 4){
            float4 P0 = *(const float4*)&Ps[warp][0][j];
            float4 P1 = *(const float4*)&Ps[warp][1][j];
#pragma unroll
            for (int jj = 0; jj < 4; jj++){
                float p0 = (&P0.x)[jj], p1 = (&P1.x)[jj];
                float v0 = Vs[j+jj][lane], v1 = Vs[j+jj][lane+32];
                o00 += p0*v0; o01 += p0*v1;
                o10 += p1*v0; o11 += p1*v1;
            }
        }
    }

    float inv0 = 1.f / l0, inv1 = 1.f / l1;
    size_t n0 = (size_t)(b*TSEQ + qg0)*DMODEL + h*DHEAD;
    size_t n1 = (size_t)(b*TSEQ + qg1)*DMODEL + h*DHEAD;
    g_h[n0 + lane]      = o00 * inv0;
    g_h[n0 + lane + 32] = o01 * inv0;
    g_h[n1 + lane]      = o10 * inv1;
    g_h[n1 + lane + 32] = o11 * inv1;
}

// ---------------- residual add + LayerNorm ----------------
__global__ void add_ln_kernel(int which, const float* __restrict__ g,
                              const float* __restrict__ bta){
    int n = blockIdx.x, tid = threadIdx.x;
    __shared__ float red[32];
    const float* addsrc = which ? g_moe : g_tmp;
    float v[4];
    float s = 0.f;
#pragma unroll
    for (int i = 0; i < 4; i++){
        int d = tid + i*256;
        v[i] = g_x[(size_t)n*DMODEL + d] + addsrc[(size_t)n*DMODEL + d];
        s += v[i];
    }
    float mean = blockRedSum(s, red) * (1.f/DMODEL);
    float vs = 0.f;
#pragma unroll
    for (int i = 0; i < 4; i++){ float dd = v[i] - mean; vs += dd*dd; }
    float var = blockRedSum(vs, red) * (1.f/DMODEL);
    float r = rsqrtf(var + 1e-5f);
#pragma unroll
    for (int i = 0; i < 4; i++){
        int d = tid + i*256;
        g_x[(size_t)n*DMODEL + d] = (v[i] - mean)*r*g[d] + bta[d];
    }
}

// ---------------- router ----------------
__global__ void gate_kernel(const float* __restrict__ W, const float* __restrict__ bb){
    int n = blockIdx.x, tid = threadIdx.x;       // 128 threads
    __shared__ float sred[NEXP][128];
    float acc[NEXP];
#pragma unroll
    for (int e = 0; e < NEXP; e++) acc[e] = 0.f;
    const float* xr = &g_x[(size_t)n*DMODEL];
    for (int d = tid; d < DMODEL; d += 128){
        float xv = xr[d];
#pragma unroll
        for (int e = 0; e < NEXP; e++) acc[e] += xv * W[d*NEXP + e];
    }
#pragma unroll
    for (int e = 0; e < NEXP; e++) sred[e][tid] = acc[e];
    __syncthreads();
    for (int s = 64; s > 0; s >>= 1){
        if (tid < s){
#pragma unroll
            for (int e = 0; e < NEXP; e++) sred[e][tid] += sred[e][tid + s];
        }
        __syncthreads();
    }
    if (tid == 0){
        float lg[NEXP], mx = -3e38f;
#pragma unroll
        for (int e = 0; e < NEXP; e++){ lg[e] = sred[e][0] + bb[e]; mx = fmaxf(mx, lg[e]); }
        float s = 0.f, p[NEXP];
#pragma unroll
        for (int e = 0; e < NEXP; e++){ p[e] = __expf(lg[e] - mx); s += p[e]; }
        float invs = 1.f / s;
#pragma unroll
        for (int e = 0; e < NEXP; e++){ p[e] *= invs; g_probs[n*NEXP + e] = p[e]; }
        int i1 = 0;
#pragma unroll
        for (int e = 1; e < NEXP; e++) if (p[e] > p[i1]) i1 = e;
        int i2 = (i1 == 0) ? 1 : 0;
#pragma unroll
        for (int e = 0; e < NEXP; e++) if (e != i1 && p[e] > p[i2]) i2 = e;
        float sw = p[i1] + p[i2];
        g_tki[n*2]   = i1; g_tki[n*2+1] = i2;
        g_tkw[n*2]   = p[i1] / sw;
        g_tkw[n*2+1] = p[i2] / sw;
        atomicAdd(&g_counts[i1], 1);
        atomicAdd(&g_counts[i2], 1);
    }
}

// ---------------- per-layer reset ----------------
__global__ void reset_kernel(){
    int i = blockIdx.x * blockDim.x + threadIdx.x;
    if (i < N_TOK*DMODEL) g_moe[i] = 0.f;
    if (i < CAP){ g_atok[i] = 0; g_aw[i] = 0.f; }
    if (i < NEXP){ g_counts[i] = 0; g_cursor[i] = 0; }
}

__global__ void scan_kernel(){
    if (threadIdx.x == 0){
        int o = 0;
        for (int e = 0; e < NEXP; e++){
            g_off[e] = o;
            o += (g_counts[e] + 127) & ~127;
        }
        g_off[NEXP] = o;
    }
}

__global__ void scatter_kernel(){
    int n = blockIdx.x * blockDim.x + threadIdx.x;
    if (n >= N_TOK) return;
#pragma unroll
    for (int k = 0; k < 2; k++){
        int e = g_tki[n*2 + k];
        int pos = atomicAdd(&g_cursor[e], 1);
        int slot = g_off[e] + pos;
        g_atok[slot] = n;
        g_aw[slot]   = g_tkw[n*2 + k];
    }
}

// ---------------- load-balance loss ----------------
__global__ void lb_part_kernel(){
    int e = blockIdx.x, tid = threadIdx.x;
    __shared__ float red[32];
    float s = 0.f;
    for (int n = tid; n < N_TOK; n += 256) s += g_probs[n*NEXP + e];
    float tot = blockRedSum(s, red);
    if (tid == 0)
        g_Pc[e] = (float)NEXP * ((float)g_counts[e] / (float)N_TOK) * (tot / (float)N_TOK);
}
__global__ void lb_acc_kernel(){
    if (threadIdx.x == 0){
        float s = 0.f;
        for (int e = 0; e < NEXP; e++) s += g_Pc[e];
        g_lb += s;
    }
}
__global__ void init_kernel(){ g_lb = 0.f; }

// ---------------- output ----------------
__global__ void finalize_kernel(float* __restrict__ out, int out_size){
    int i = blockIdx.x * blockDim.x + threadIdx.x;
    if (i >= out_size) return;
    if (i < N_TOK*DMODEL) out[i] = g_x[i];
    else                  out[i] = g_lb;
}

// ---------------- host orchestration ----------------
extern "C" void kernel_launch(void* const* d_in, const int* in_sizes, int n_in,
                              void* d_out, int out_size)
{
    const int*   ids  = (const int*)  d_in[0];
    const int*   am   = (const int*)  d_in[1];
    const float* emb  = (const float*)d_in[2];
    const float* pos  = (const float*)d_in[3];
    const float* Wqkv = (const float*)d_in[4];
    const float* bqkv = (const float*)d_in[5];
    const float* Wo   = (const float*)d_in[6];
    const float* bo   = (const float*)d_in[7];
    const float* ln1g = (const float*)d_in[8];
    const float* ln1b = (const float*)d_in[9];
    const float* ln2g = (const float*)d_in[10];
    const float* ln2b = (const float*)d_in[11];
    const float* gW   = (const float*)d_in[12];
    const float* gb   = (const float*)d_in[13];
    const float* W1   = (const float*)d_in[14];
    const float* b1   = (const float*)d_in[15];
    const float* W2   = (const float*)d_in[16];
    const float* b2   = (const float*)d_in[17];

    init_kernel<<<1, 1>>>();
    embed_kernel<<<N_TOK, 256>>>(ids, emb, pos);

    for (int l = 0; l < NLAYER; l++){
        mma_gemm<0><<<dim3(QKVD/128, N_TOK/128), 256>>>(
            Wqkv + (size_t)l*DMODEL*QKVD, bqkv + (size_t)l*QKVD, QKVD, DMODEL);
        attn_kernel<<<dim3(TSEQ/16, NHEAD, BATCH), 256>>>(am);
        mma_gemm<1><<<dim3(DMODEL/128, N_TOK/128), 256>>>(
            Wo + (size_t)l*DMODEL*DMODEL, bo + (size_t)l*DMODEL, DMODEL, DMODEL);
        add_ln_kernel<<<N_TOK, 256>>>(0, ln1g + (size_t)l*DMODEL, ln1b + (size_t)l*DMODEL);

        reset_kernel<<<(N_TOK*DMODEL + 255)/256, 256>>>();
        gate_kernel<<<N_TOK, 128>>>(gW + (size_t)l*DMODEL*NEXP, gb + (size_t)l*NEXP);
        scan_kernel<<<1, 1>>>();
        scatter_kernel<<<(N_TOK + 255)/256, 256>>>();

        mma_gemm<2><<<dim3(HFF/128, CAP/128), 256>>>(
            W1 + (size_t)l*NEXP*DMODEL*HFF, b1 + (size_t)l*NEXP*HFF, HFF, DMODEL);
        mma_gemm<3><<<dim3(DMODEL/128, CAP/128), 256>>>(
            W2 + (size_t)l*NEXP*HFF*DMODEL, b2 + (size_t)l*NEXP*DMODEL, DMODEL, HFF);

        lb_part_kernel<<<NEXP, 256>>>();
        lb_acc_kernel<<<1, 1>>>();

        add_ln_kernel<<<N_TOK, 256>>>(1, ln2g + (size_t)l*DMODEL, ln2b + (size_t)l*DMODEL);
    }

    int total = out_size > N_TOK*DMODEL ? out_size : N_TOK*DMODEL;
    finalize_kernel<<<(total + 255)/256, 256>>>((float*)d_out, out_size);
}

// round 4
// speedup vs baseline: 1.7520x; 1.3938x over previous
#include <cuda_runtime.h>
#include <cuda_bf16.h>
#include <math.h>

#define N_TOK   8192
#define DMODEL  1024
#define QKVD    3072
#define NHEAD   16
#define DHEAD   64
#define NEXP    8
#define HFF     4096
#define TSEQ    1024
#define BATCH   8
#define NLAYER  2
#define CAP     17408   // 16384 assignments + 8*128 alignment pad

// ---------------- device scratch ----------------
__device__ float g_x[N_TOK*DMODEL];
__device__ float g_qkv[(size_t)N_TOK*QKVD];
__device__ float g_h[N_TOK*DMODEL];
__device__ float g_tmp[N_TOK*DMODEL];
__device__ float g_moe[N_TOK*DMODEL];
__device__ float g_h1[(size_t)CAP*HFF];
__device__ float g_probs[N_TOK*NEXP];
__device__ int   g_tki[N_TOK*2];
__device__ float g_tkw[N_TOK*2];
__device__ int   g_counts[NEXP];
__device__ int   g_cursor[NEXP];
__device__ int   g_off[NEXP+1];
__device__ int   g_atok[CAP];
__device__ float g_aw[CAP];
__device__ float g_Pc[NEXP];
__device__ float g_lb;

// ---------------- reductions ----------------
__device__ __forceinline__ float warpRedSum(float v){
#pragma unroll
    for (int o = 16; o; o >>= 1) v += __shfl_xor_sync(0xffffffffu, v, o);
    return v;
}
__device__ __forceinline__ float warpRedMax(float v){
#pragma unroll
    for (int o = 16; o; o >>= 1) v = fmaxf(v, __shfl_xor_sync(0xffffffffu, v, o));
    return v;
}
__device__ float blockRedSum(float v, float* red){
    int lane = threadIdx.x & 31, w = threadIdx.x >> 5, nw = blockDim.x >> 5;
    __syncthreads();
    v = warpRedSum(v);
    if (lane == 0) red[w] = v;
    __syncthreads();
    if (w == 0){
        float x = (lane < nw) ? red[lane] : 0.f;
        x = warpRedSum(x);
        if (lane == 0) red[0] = x;
    }
    __syncthreads();
    return red[0];
}

// ---------------- bf16 split helpers ----------------
__device__ __forceinline__ __nv_bfloat162 hi2(float a, float b){
    return __nv_bfloat162(__float2bfloat16(a), __float2bfloat16(b));
}
__device__ __forceinline__ __nv_bfloat162 lo2(float a, float b){
    float ha = __bfloat162float(__float2bfloat16(a));
    float hb = __bfloat162float(__float2bfloat16(b));
    return __nv_bfloat162(__float2bfloat16(a - ha), __float2bfloat16(b - hb));
}
__device__ __forceinline__ void mma_bf16(float c[4], const unsigned a[4], const unsigned b[2]){
    asm volatile("mma.sync.aligned.m16n8k16.row.col.f32.bf16.bf16.f32 "
        "{%0,%1,%2,%3}, {%4,%5,%6,%7}, {%8,%9}, {%0,%1,%2,%3};"
        : "+f"(c[0]), "+f"(c[1]), "+f"(c[2]), "+f"(c[3])
        : "r"(a[0]), "r"(a[1]), "r"(a[2]), "r"(a[3]), "r"(b[0]), "r"(b[1]));
}

// ---------------- embedding + positional ----------------
__global__ void embed_kernel(const int* __restrict__ ids,
                             const float* __restrict__ emb,
                             const float* __restrict__ pos){
    int n = blockIdx.x, tid = threadIdx.x;
    int t = n & (TSEQ - 1);
    int id = ids[n];
#pragma unroll
    for (int i = 0; i < 4; i++){
        int d = tid + i * 256;
        g_x[(size_t)n*DMODEL + d] = emb[(size_t)id*DMODEL + d] + pos[(size_t)t*DMODEL + d];
    }
}

// ------------- bf16x3 split-fp32 tensor-core GEMM, 128x128 tile, BK=16 -------------
// MODE 0: g_qkv = g_x @ B + bias                (N=3072, K=1024)
// MODE 1: g_tmp = g_h @ B + bias                (N=1024, K=1024)
// MODE 2: g_h1  = relu(gather(g_x) @ B[e]+b[e]) (N=4096, K=1024) per-expert
// MODE 3: g_moe += w * (g_h1 @ B[e] + b[e])     (N=1024, K=4096) scatter
#define KPAD 20
template<int MODE>
__global__ void __launch_bounds__(256)
mma_gemm(const float* __restrict__ Bmat, const float* __restrict__ biasB,
         int N, int K)
{
    int bn = blockIdx.x * 128;
    int bm = blockIdx.y * 128;
    int tid  = threadIdx.x;
    int warp = tid >> 5, lane = tid & 31;
    int wm = warp >> 1, wn = warp & 1;

    int e = 0, rowLimit = 0;
    if (MODE == 2 || MODE == 3){
        if (bm >= g_off[NEXP]) return;
#pragma unroll
        for (int i = 1; i < NEXP; i++) if (bm >= g_off[i]) e = i;
        rowLimit = g_off[e] + g_counts[e];
        Bmat  += (size_t)e * K * N;
        biasB += (size_t)e * N;
    }

    // A: [m][k] row-major (k contiguous).  B: [n][k] (k contiguous, transposed at store)
    __shared__ __align__(16) __nv_bfloat16 Ah[128][KPAD];
    __shared__ __align__(16) __nv_bfloat16 Al[128][KPAD];
    __shared__ __align__(16) __nv_bfloat16 Bh[128][KPAD];
    __shared__ __align__(16) __nv_bfloat16 Bl[128][KPAD];

    // global-load mapping
    int r0 = tid >> 2, r1 = r0 + 64;       // A rows
    int k4 = (tid & 3) * 4;                // A k-offset
    int kb0 = tid >> 5, kb1 = kb0 + 8;     // B k rows
    int cb  = (tid & 31) * 4;              // B n-offset

    const float *Ap0, *Ap1;
    if      (MODE == 0){ Ap0 = &g_x [(size_t)(bm + r0) * DMODEL]; Ap1 = &g_x [(size_t)(bm + r1) * DMODEL]; }
    else if (MODE == 1){ Ap0 = &g_h [(size_t)(bm + r0) * DMODEL]; Ap1 = &g_h [(size_t)(bm + r1) * DMODEL]; }
    else if (MODE == 2){ Ap0 = &g_x [(size_t)g_atok[bm + r0] * DMODEL]; Ap1 = &g_x [(size_t)g_atok[bm + r1] * DMODEL]; }
    else               { Ap0 = &g_h1[(size_t)(bm + r0) * HFF];    Ap1 = &g_h1[(size_t)(bm + r1) * HFF]; }

    const float* Bp0 = Bmat + (size_t)kb0 * N + bn + cb;
    const float* Bp1 = Bmat + (size_t)kb1 * N + bn + cb;

    float acc[2][8][4];
#pragma unroll
    for (int mt = 0; mt < 2; mt++)
#pragma unroll
        for (int nt = 0; nt < 8; nt++)
#pragma unroll
            for (int i = 0; i < 4; i++) acc[mt][nt][i] = 0.f;

    float4 pa0 = *(const float4*)(Ap0 + k4);
    float4 pa1 = *(const float4*)(Ap1 + k4);
    float4 pb0 = *(const float4*)Bp0;
    float4 pb1 = *(const float4*)Bp1;

    int rql = lane >> 2, rqm = lane & 3;   // groupID / thread-in-group
    int kq = rqm * 2;

    for (int k0 = 0; k0 < K; k0 += 16){
        // ---- stage smem (split hi/lo) ----
        *(__nv_bfloat162*)&Ah[r0][k4]   = hi2(pa0.x, pa0.y);
        *(__nv_bfloat162*)&Ah[r0][k4+2] = hi2(pa0.z, pa0.w);
        *(__nv_bfloat162*)&Al[r0][k4]   = lo2(pa0.x, pa0.y);
        *(__nv_bfloat162*)&Al[r0][k4+2] = lo2(pa0.z, pa0.w);
        *(__nv_bfloat162*)&Ah[r1][k4]   = hi2(pa1.x, pa1.y);
        *(__nv_bfloat162*)&Ah[r1][k4+2] = hi2(pa1.z, pa1.w);
        *(__nv_bfloat162*)&Al[r1][k4]   = lo2(pa1.x, pa1.y);
        *(__nv_bfloat162*)&Al[r1][k4+2] = lo2(pa1.z, pa1.w);
        // B transposed: Bs[n][k]
        {
            float v[4] = {pb0.x, pb0.y, pb0.z, pb0.w};
#pragma unroll
            for (int i = 0; i < 4; i++){
                float h = __bfloat162float(__float2bfloat16(v[i]));
                Bh[cb+i][kb0] = __float2bfloat16(v[i]);
                Bl[cb+i][kb0] = __float2bfloat16(v[i] - h);
            }
            float w[4] = {pb1.x, pb1.y, pb1.z, pb1.w};
#pragma unroll
            for (int i = 0; i < 4; i++){
                float h = __bfloat162float(__float2bfloat16(w[i]));
                Bh[cb+i][kb1] = __float2bfloat16(w[i]);
                Bl[cb+i][kb1] = __float2bfloat16(w[i] - h);
            }
        }
        __syncthreads();
        if (k0 + 16 < K){
            pa0 = *(const float4*)(Ap0 + k0 + 16 + k4);
            pa1 = *(const float4*)(Ap1 + k0 + 16 + k4);
            pb0 = *(const float4*)(Bp0 + (size_t)16 * N);
            pb1 = *(const float4*)(Bp1 + (size_t)16 * N);
            Bp0 += (size_t)16 * N; Bp1 += (size_t)16 * N;
        }

        // ---- fragments + MMA ----
        unsigned ah[2][4], al[2][4];
#pragma unroll
        for (int mt = 0; mt < 2; mt++){
            int r = wm*32 + mt*16 + rql;
            ah[mt][0] = *(const unsigned*)&Ah[r  ][kq];
            ah[mt][1] = *(const unsigned*)&Ah[r+8][kq];
            ah[mt][2] = *(const unsigned*)&Ah[r  ][kq+8];
            ah[mt][3] = *(const unsigned*)&Ah[r+8][kq+8];
            al[mt][0] = *(const unsigned*)&Al[r  ][kq];
            al[mt][1] = *(const unsigned*)&Al[r+8][kq];
            al[mt][2] = *(const unsigned*)&Al[r  ][kq+8];
            al[mt][3] = *(const unsigned*)&Al[r+8][kq+8];
        }
        unsigned bh[8][2], bl[8][2];
#pragma unroll
        for (int nt = 0; nt < 8; nt++){
            int c = wn*64 + nt*8 + rql;
            bh[nt][0] = *(const unsigned*)&Bh[c][kq];
            bh[nt][1] = *(const unsigned*)&Bh[c][kq+8];
            bl[nt][0] = *(const unsigned*)&Bl[c][kq];
            bl[nt][1] = *(const unsigned*)&Bl[c][kq+8];
        }
#pragma unroll
        for (int mt = 0; mt < 2; mt++)
#pragma unroll
            for (int nt = 0; nt < 8; nt++){
                mma_bf16(acc[mt][nt], ah[mt], bh[nt]);   // hi*hi
                mma_bf16(acc[mt][nt], ah[mt], bl[nt]);   // hi*lo
                mma_bf16(acc[mt][nt], al[mt], bh[nt]);   // lo*hi
            }
        __syncthreads();
    }

    // epilogue. fragment: c0=(r,c) c1=(r,c+1) c2=(r+8,c) c3=(r+8,c+1)
    int c_lo = 2 * rqm;
#pragma unroll
    for (int mt = 0; mt < 2; mt++){
        int grA = bm + wm*32 + mt*16 + rql;
        int grB = grA + 8;
        if (MODE == 3){
            bool okA = grA < rowLimit, okB = grB < rowLimit;
            int   tokA = okA ? g_atok[grA] : 0;  float wA = okA ? g_aw[grA] : 0.f;
            int   tokB = okB ? g_atok[grB] : 0;  float wB = okB ? g_aw[grB] : 0.f;
#pragma unroll
            for (int nt = 0; nt < 8; nt++){
                int gc = bn + wn*64 + nt*8 + c_lo;
                float b0 = biasB[gc], b1 = biasB[gc+1];
                if (okA){
                    atomicAdd(&g_moe[(size_t)tokA*DMODEL + gc    ], wA*(acc[mt][nt][0] + b0));
                    atomicAdd(&g_moe[(size_t)tokA*DMODEL + gc + 1], wA*(acc[mt][nt][1] + b1));
                }
                if (okB){
                    atomicAdd(&g_moe[(size_t)tokB*DMODEL + gc    ], wB*(acc[mt][nt][2] + b0));
                    atomicAdd(&g_moe[(size_t)tokB*DMODEL + gc + 1], wB*(acc[mt][nt][3] + b1));
                }
            }
        } else {
#pragma unroll
            for (int nt = 0; nt < 8; nt++){
                int gc = bn + wn*64 + nt*8 + c_lo;
                float b0 = biasB[gc], b1 = biasB[gc+1];
                float v0 = acc[mt][nt][0] + b0, v1 = acc[mt][nt][1] + b1;
                float v2 = acc[mt][nt][2] + b0, v3 = acc[mt][nt][3] + b1;
                if (MODE == 0){
                    g_qkv[(size_t)grA*QKVD + gc] = v0; g_qkv[(size_t)grA*QKVD + gc+1] = v1;
                    g_qkv[(size_t)grB*QKVD + gc] = v2; g_qkv[(size_t)grB*QKVD + gc+1] = v3;
                } else if (MODE == 1){
                    g_tmp[(size_t)grA*DMODEL + gc] = v0; g_tmp[(size_t)grA*DMODEL + gc+1] = v1;
                    g_tmp[(size_t)grB*DMODEL + gc] = v2; g_tmp[(size_t)grB*DMODEL + gc+1] = v3;
                } else {
                    g_h1[(size_t)grA*HFF + gc]   = fmaxf(v0, 0.f);
                    g_h1[(size_t)grA*HFF + gc+1] = fmaxf(v1, 0.f);
                    g_h1[(size_t)grB*HFF + gc]   = fmaxf(v2, 0.f);
                    g_h1[(size_t)grB*HFF + gc+1] = fmaxf(v3, 0.f);
                }
            }
        }
    }
}

// ---------------- flash attention: 16 queries x 64-key tiles ----------------
__global__ void __launch_bounds__(256)
attn_kernel(const int* __restrict__ amask){
    int qt = blockIdx.x, h = blockIdx.y, b = blockIdx.z;
    int tid = threadIdx.x, warp = tid >> 5, lane = tid & 31;
    int qbase = qt * 16;

    __shared__ __align__(16) float Qs[16][68];
    __shared__ __align__(16) float Ks[64][68];
    __shared__ __align__(16) float Vs[64][68];
    __shared__ __align__(16) float Ps[8][2][68];

    {
        int q = tid >> 4, d4 = (tid & 15) * 4;
        const float* src = &g_qkv[(size_t)(b*TSEQ + qbase + q)*QKVD + h*DHEAD + d4];
        float4 v = *(const float4*)src;
        Qs[q][d4] = v.x*0.125f; Qs[q][d4+1] = v.y*0.125f;
        Qs[q][d4+2] = v.z*0.125f; Qs[q][d4+3] = v.w*0.125f;
    }

    int qg0 = qbase + warp*2, qg1 = qg0 + 1;
    float m0 = -3.0e38f, m1 = -3.0e38f;
    float l0 = 0.f, l1 = 0.f;
    float o00 = 0.f, o01 = 0.f, o10 = 0.f, o11 = 0.f;

    int ntiles = (qbase + 15) / 64 + 1;
    for (int tile = 0; tile < ntiles; tile++){
        int j0 = tile * 64;
        __syncthreads();
#pragma unroll
        for (int p = 0; p < 4; p++){
            int idx = tid + p*256;
            int row = idx >> 4, d4 = (idx & 15)*4;
            size_t base = (size_t)(b*TSEQ + j0 + row)*QKVD + h*DHEAD + d4;
            *(float4*)&Ks[row][d4] = *(const float4*)&g_qkv[base + DMODEL];
            *(float4*)&Vs[row][d4] = *(const float4*)&g_qkv[base + 2*DMODEL];
        }
        __syncthreads();

        float s00=0.f, s01=0.f, s10=0.f, s11=0.f;
#pragma unroll
        for (int d = 0; d < 64; d += 4){
            float4 ka = *(const float4*)&Ks[lane][d];
            float4 kb = *(const float4*)&Ks[lane+32][d];
            float4 qa = *(const float4*)&Qs[warp*2][d];
            float4 qb = *(const float4*)&Qs[warp*2+1][d];
            s00 += qa.x*ka.x + qa.y*ka.y + qa.z*ka.z + qa.w*ka.w;
            s01 += qa.x*kb.x + qa.y*kb.y + qa.z*kb.z + qa.w*kb.w;
            s10 += qb.x*ka.x + qb.y*ka.y + qb.z*ka.z + qb.w*ka.w;
            s11 += qb.x*kb.x + qb.y*kb.y + qb.z*kb.z + qb.w*kb.w;
        }
        int j1 = j0 + lane, j2 = j0 + lane + 32;
        int am1 = amask[b*TSEQ + j1], am2 = amask[b*TSEQ + j2];
        if (j1 > qg0 || !am1) s00 = -1e9f;
        if (j2 > qg0 || !am2) s01 = -1e9f;
        if (j1 > qg1 || !am1) s10 = -1e9f;
        if (j2 > qg1 || !am2) s11 = -1e9f;

        {
            float tm = warpRedMax(fmaxf(s00, s01));
            float mn = fmaxf(m0, tm);
            float sc = __expf(m0 - mn);
            float pA = __expf(s00 - mn), pB = __expf(s01 - mn);
            l0 = l0*sc + warpRedSum(pA + pB);
            o00 *= sc; o01 *= sc; m0 = mn;
            Ps[warp][0][lane] = pA; Ps[warp][0][lane+32] = pB;
        }
        {
            float tm = warpRedMax(fmaxf(s10, s11));
            float mn = fmaxf(m1, tm);
            float sc = __expf(m1 - mn);
            float pA = __expf(s10 - mn), pB = __expf(s11 - mn);
            l1 = l1*sc + warpRedSum(pA + pB);
            o10 *= sc; o11 *= sc; m1 = mn;
            Ps[warp][1][lane] = pA; Ps[warp][1][lane+32] = pB;
        }
        __syncwarp();

#pragma unroll 4
        for (int j = 0; j < 64; j += 4){
            float4 P0 = *(const float4*)&Ps[warp][0][j];
            float4 P1 = *(const float4*)&Ps[warp][1][j];
#pragma unroll
            for (int jj = 0; jj < 4; jj++){
                float p0 = (&P0.x)[jj], p1 = (&P1.x)[jj];
                float v0 = Vs[j+jj][lane], v1 = Vs[j+jj][lane+32];
                o00 += p0*v0; o01 += p0*v1;
                o10 += p1*v0; o11 += p1*v1;
            }
        }
    }

    float inv0 = 1.f / l0, inv1 = 1.f / l1;
    size_t n0 = (size_t)(b*TSEQ + qg0)*DMODEL + h*DHEAD;
    size_t n1 = (size_t)(b*TSEQ + qg1)*DMODEL + h*DHEAD;
    g_h[n0 + lane]      = o00 * inv0;
    g_h[n0 + lane + 32] = o01 * inv0;
    g_h[n1 + lane]      = o10 * inv1;
    g_h[n1 + lane + 32] = o11 * inv1;
}

// ---------------- residual add + LayerNorm ----------------
__global__ void add_ln_kernel(int which, const float* __restrict__ g,
                              const float* __restrict__ bta){
    int n = blockIdx.x, tid = threadIdx.x;
    __shared__ float red[32];
    const float* addsrc = which ? g_moe : g_tmp;
    float v[4];
    float s = 0.f;
#pragma unroll
    for (int i = 0; i < 4; i++){
        int d = tid + i*256;
        v[i] = g_x[(size_t)n*DMODEL + d] + addsrc[(size_t)n*DMODEL + d];
        s += v[i];
    }
    float mean = blockRedSum(s, red) * (1.f/DMODEL);
    float vs = 0.f;
#pragma unroll
    for (int i = 0; i < 4; i++){ float dd = v[i] - mean; vs += dd*dd; }
    float var = blockRedSum(vs, red) * (1.f/DMODEL);
    float r = rsqrtf(var + 1e-5f);
#pragma unroll
    for (int i = 0; i < 4; i++){
        int d = tid + i*256;
        g_x[(size_t)n*DMODEL + d] = (v[i] - mean)*r*g[d] + bta[d];
    }
}

// ---------------- router ----------------
__global__ void gate_kernel(const float* __restrict__ W, const float* __restrict__ bb){
    int n = blockIdx.x, tid = threadIdx.x;       // 128 threads
    __shared__ float sred[NEXP][128];
    float acc[NEXP];
#pragma unroll
    for (int e = 0; e < NEXP; e++) acc[e] = 0.f;
    const float* xr = &g_x[(size_t)n*DMODEL];
    for (int d = tid; d < DMODEL; d += 128){
        float xv = xr[d];
#pragma unroll
        for (int e = 0; e < NEXP; e++) acc[e] += xv * W[d*NEXP + e];
    }
#pragma unroll
    for (int e = 0; e < NEXP; e++) sred[e][tid] = acc[e];
    __syncthreads();
    for (int s = 64; s > 0; s >>= 1){
        if (tid < s){
#pragma unroll
            for (int e = 0; e < NEXP; e++) sred[e][tid] += sred[e][tid + s];
        }
        __syncthreads();
    }
    if (tid == 0){
        float lg[NEXP], mx = -3e38f;
#pragma unroll
        for (int e = 0; e < NEXP; e++){ lg[e] = sred[e][0] + bb[e]; mx = fmaxf(mx, lg[e]); }
        float s = 0.f, p[NEXP];
#pragma unroll
        for (int e = 0; e < NEXP; e++){ p[e] = __expf(lg[e] - mx); s += p[e]; }
        float invs = 1.f / s;
#pragma unroll
        for (int e = 0; e < NEXP; e++){ p[e] *= invs; g_probs[n*NEXP + e] = p[e]; }
        int i1 = 0;
#pragma unroll
        for (int e = 1; e < NEXP; e++) if (p[e] > p[i1]) i1 = e;
        int i2 = (i1 == 0) ? 1 : 0;
#pragma unroll
        for (int e = 0; e < NEXP; e++) if (e != i1 && p[e] > p[i2]) i2 = e;
        float sw = p[i1] + p[i2];
        g_tki[n*2]   = i1; g_tki[n*2+1] = i2;
        g_tkw[n*2]   = p[i1] / sw;
        g_tkw[n*2+1] = p[i2] / sw;
        atomicAdd(&g_counts[i1], 1);
        atomicAdd(&g_counts[i2], 1);
    }
}

// ---------------- per-layer reset ----------------
__global__ void reset_kernel(){
    int i = blockIdx.x * blockDim.x + threadIdx.x;
    if (i < N_TOK*DMODEL) g_moe[i] = 0.f;
    if (i < CAP){ g_atok[i] = 0; g_aw[i] = 0.f; }
    if (i < NEXP){ g_counts[i] = 0; g_cursor[i] = 0; }
}

__global__ void scan_kernel(){
    if (threadIdx.x == 0){
        int o = 0;
        for (int e = 0; e < NEXP; e++){
            g_off[e] = o;
            o += (g_counts[e] + 127) & ~127;
        }
        g_off[NEXP] = o;
    }
}

__global__ void scatter_kernel(){
    int n = blockIdx.x * blockDim.x + threadIdx.x;
    if (n >= N_TOK) return;
#pragma unroll
    for (int k = 0; k < 2; k++){
        int e = g_tki[n*2 + k];
        int pos = atomicAdd(&g_cursor[e], 1);
        int slot = g_off[e] + pos;
        g_atok[slot] = n;
        g_aw[slot]   = g_tkw[n*2 + k];
    }
}

// ---------------- load-balance loss ----------------
__global__ void lb_part_kernel(){
    int e = blockIdx.x, tid = threadIdx.x;
    __shared__ float red[32];
    float s = 0.f;
    for (int n = tid; n < N_TOK; n += 256) s += g_probs[n*NEXP + e];
    float tot = blockRedSum(s, red);
    if (tid == 0)
        g_Pc[e] = (float)NEXP * ((float)g_counts[e] / (float)N_TOK) * (tot / (float)N_TOK);
}
__global__ void lb_acc_kernel(){
    if (threadIdx.x == 0){
        float s = 0.f;
        for (int e = 0; e < NEXP; e++) s += g_Pc[e];
        g_lb += s;
    }
}
__global__ void init_kernel(){ g_lb = 0.f; }

// ---------------- output ----------------
__global__ void finalize_kernel(float* __restrict__ out, int out_size){
    int i = blockIdx.x * blockDim.x + threadIdx.x;
    if (i >= out_size) return;
    if (i < N_TOK*DMODEL) out[i] = g_x[i];
    else                  out[i] = g_lb;
}

// ---------------- host orchestration ----------------
extern "C" void kernel_launch(void* const* d_in, const int* in_sizes, int n_in,
                              void* d_out, int out_size)
{
    const int*   ids  = (const int*)  d_in[0];
    const int*   am   = (const int*)  d_in[1];
    const float* emb  = (const float*)d_in[2];
    const float* pos  = (const float*)d_in[3];
    const float* Wqkv = (const float*)d_in[4];
    const float* bqkv = (const float*)d_in[5];
    const float* Wo   = (const float*)d_in[6];
    const float* bo   = (const float*)d_in[7];
    const float* ln1g = (const float*)d_in[8];
    const float* ln1b = (const float*)d_in[9];
    const float* ln2g = (const float*)d_in[10];
    const float* ln2b = (const float*)d_in[11];
    const float* gW   = (const float*)d_in[12];
    const float* gb   = (const float*)d_in[13];
    const float* W1   = (const float*)d_in[14];
    const float* b1   = (const float*)d_in[15];
    const float* W2   = (const float*)d_in[16];
    const float* b2   = (const float*)d_in[17];

    init_kernel<<<1, 1>>>();
    embed_kernel<<<N_TOK, 256>>>(ids, emb, pos);

    for (int l = 0; l < NLAYER; l++){
        mma_gemm<0><<<dim3(QKVD/128, N_TOK/128), 256>>>(
            Wqkv + (size_t)l*DMODEL*QKVD, bqkv + (size_t)l*QKVD, QKVD, DMODEL);
        attn_kernel<<<dim3(TSEQ/16, NHEAD, BATCH), 256>>>(am);
        mma_gemm<1><<<dim3(DMODEL/128, N_TOK/128), 256>>>(
            Wo + (size_t)l*DMODEL*DMODEL, bo + (size_t)l*DMODEL, DMODEL, DMODEL);
        add_ln_kernel<<<N_TOK, 256>>>(0, ln1g + (size_t)l*DMODEL, ln1b + (size_t)l*DMODEL);

        reset_kernel<<<(N_TOK*DMODEL + 255)/256, 256>>>();
        gate_kernel<<<N_TOK, 128>>>(gW + (size_t)l*DMODEL*NEXP, gb + (size_t)l*NEXP);
        scan_kernel<<<1, 1>>>();
        scatter_kernel<<<(N_TOK + 255)/256, 256>>>();

        mma_gemm<2><<<dim3(HFF/128, CAP/128), 256>>>(
            W1 + (size_t)l*NEXP*DMODEL*HFF, b1 + (size_t)l*NEXP*HFF, HFF, DMODEL);
        mma_gemm<3><<<dim3(DMODEL/128, CAP/128), 256>>>(
            W2 + (size_t)l*NEXP*HFF*DMODEL, b2 + (size_t)l*NEXP*DMODEL, DMODEL, HFF);

        lb_part_kernel<<<NEXP, 256>>>();
        lb_acc_kernel<<<1, 1>>>();

        add_ln_kernel<<<N_TOK, 256>>>(1, ln2g + (size_t)l*DMODEL, ln2b + (size_t)l*DMODEL);
    }

    int total = out_size > N_TOK*DMODEL ? out_size : N_TOK*DMODEL;
    finalize_kernel<<<(total + 255)/256, 256>>>((float*)d_out, out_size);
}

// round 5
// speedup vs baseline: 3.0385x; 1.7343x over previous
#include <cuda_runtime.h>
#include <cuda_bf16.h>
#include <math.h>

#define N_TOK   8192
#define DMODEL  1024
#define QKVD    3072
#define NHEAD   16
#define DHEAD   64
#define NEXP    8
#define HFF     4096
#define TSEQ    1024
#define BATCH   8
#define NLAYER  2
#define CAP     17408   // 16384 assignments + 8*128 alignment pad

// ---------------- device scratch ----------------
__device__ float g_x[N_TOK*DMODEL];
__device__ float g_qkv[(size_t)N_TOK*QKVD];
__device__ float g_h[N_TOK*DMODEL];
__device__ float g_tmp[N_TOK*DMODEL];
__device__ float g_moe[N_TOK*DMODEL];
__device__ float g_h1[(size_t)CAP*HFF];
__device__ float g_probs[N_TOK*NEXP];
__device__ int   g_tki[N_TOK*2];
__device__ float g_tkw[N_TOK*2];
__device__ int   g_counts[NEXP];
__device__ int   g_cursor[NEXP];
__device__ int   g_off[NEXP+1];
__device__ int   g_atok[CAP];
__device__ float g_aw[CAP];
__device__ float g_Pc[NEXP];
__device__ float g_lb;

// ---------------- reductions ----------------
__device__ __forceinline__ float warpRedSum(float v){
#pragma unroll
    for (int o = 16; o; o >>= 1) v += __shfl_xor_sync(0xffffffffu, v, o);
    return v;
}
__device__ __forceinline__ float warpRedMax(float v){
#pragma unroll
    for (int o = 16; o; o >>= 1) v = fmaxf(v, __shfl_xor_sync(0xffffffffu, v, o));
    return v;
}
__device__ float blockRedSum(float v, float* red){
    int lane = threadIdx.x & 31, w = threadIdx.x >> 5, nw = blockDim.x >> 5;
    __syncthreads();
    v = warpRedSum(v);
    if (lane == 0) red[w] = v;
    __syncthreads();
    if (w == 0){
        float x = (lane < nw) ? red[lane] : 0.f;
        x = warpRedSum(x);
        if (lane == 0) red[0] = x;
    }
    __syncthreads();
    return red[0];
}

// ---------------- bf16 helpers ----------------
__device__ __forceinline__ unsigned hi2u(float a, float b){
    __nv_bfloat162 h(__float2bfloat16(a), __float2bfloat16(b));
    return *(unsigned*)&h;
}
__device__ __forceinline__ unsigned lo2u(float a, float b){
    float ha = __bfloat162float(__float2bfloat16(a));
    float hb = __bfloat162float(__float2bfloat16(b));
    __nv_bfloat162 l(__float2bfloat16(a - ha), __float2bfloat16(b - hb));
    return *(unsigned*)&l;
}
__device__ __forceinline__ void mma_bf16(float c[4], const unsigned a[4],
                                         unsigned b0, unsigned b1){
    asm volatile("mma.sync.aligned.m16n8k16.row.col.f32.bf16.bf16.f32 "
        "{%0,%1,%2,%3}, {%4,%5,%6,%7}, {%8,%9}, {%0,%1,%2,%3};"
        : "+f"(c[0]), "+f"(c[1]), "+f"(c[2]), "+f"(c[3])
        : "r"(a[0]), "r"(a[1]), "r"(a[2]), "r"(a[3]), "r"(b0), "r"(b1));
}
__device__ __forceinline__ void ldsm4(unsigned r[4], const __nv_bfloat16* p){
    unsigned addr = (unsigned)__cvta_generic_to_shared((void*)p);
    asm volatile("ldmatrix.sync.aligned.m8n8.x4.shared.b16 {%0,%1,%2,%3}, [%4];"
        : "=r"(r[0]), "=r"(r[1]), "=r"(r[2]), "=r"(r[3]) : "r"(addr));
}
__device__ __forceinline__ void ldsm4t(unsigned r[4], const __nv_bfloat16* p){
    unsigned addr = (unsigned)__cvta_generic_to_shared((void*)p);
    asm volatile("ldmatrix.sync.aligned.m8n8.x4.trans.shared.b16 {%0,%1,%2,%3}, [%4];"
        : "=r"(r[0]), "=r"(r[1]), "=r"(r[2]), "=r"(r[3]) : "r"(addr));
}

// ---------------- embedding + positional ----------------
__global__ void embed_kernel(const int* __restrict__ ids,
                             const float* __restrict__ emb,
                             const float* __restrict__ pos){
    int n = blockIdx.x, tid = threadIdx.x;
    int t = n & (TSEQ - 1);
    int id = ids[n];
#pragma unroll
    for (int i = 0; i < 4; i++){
        int d = tid + i * 256;
        g_x[(size_t)n*DMODEL + d] = emb[(size_t)id*DMODEL + d] + pos[(size_t)t*DMODEL + d];
    }
}

// ------- bf16x3 split-fp32 tensor-core GEMM, 128x128 tile, BK=16 -------
// ldmatrix fragment loads + double-buffered smem.
// MODE 0: g_qkv = g_x @ B + bias                (N=3072, K=1024)
// MODE 1: g_tmp = g_h @ B + bias                (N=1024, K=1024)
// MODE 2: g_h1  = relu(gather(g_x) @ B[e]+b[e]) (N=4096, K=1024) per-expert
// MODE 3: g_moe += w * (g_h1 @ B[e] + b[e])     (N=1024, K=4096) scatter
#define APAD 24    // A row stride (bf16): 48B -> conflict-free ldmatrix
#define BPAD 136   // B row stride (bf16): 272B -> conflict-free ldmatrix.trans
template<int MODE>
__global__ void __launch_bounds__(256)
mma_gemm(const float* __restrict__ Bmat, const float* __restrict__ biasB,
         int N, int K)
{
    int bn = blockIdx.x * 128;
    int bm = blockIdx.y * 128;
    int tid  = threadIdx.x;
    int warp = tid >> 5, lane = tid & 31;
    int wm = warp >> 1, wn = warp & 1;

    int e = 0, rowLimit = 0;
    if (MODE == 2 || MODE == 3){
        if (bm >= g_off[NEXP]) return;
#pragma unroll
        for (int i = 1; i < NEXP; i++) if (bm >= g_off[i]) e = i;
        rowLimit = g_off[e] + g_counts[e];
        Bmat  += (size_t)e * K * N;
        biasB += (size_t)e * N;
    }

    // A: [m][k] (k contiguous).  B: [k][n] (n contiguous). Double buffered.
    __shared__ __align__(16) __nv_bfloat16 Ah[2][128][APAD];
    __shared__ __align__(16) __nv_bfloat16 Al[2][128][APAD];
    __shared__ __align__(16) __nv_bfloat16 Bh[2][16][BPAD];
    __shared__ __align__(16) __nv_bfloat16 Bl[2][16][BPAD];

    // global-load mapping
    int r0 = tid >> 2, r1 = r0 + 64;       // A rows
    int k4 = (tid & 3) * 4;                // A k-offset
    int kb0 = tid >> 5, kb1 = kb0 + 8;     // B k rows
    int cb  = (tid & 31) * 4;              // B n-offset

    const float *Ap0, *Ap1;
    if      (MODE == 0){ Ap0 = &g_x [(size_t)(bm + r0) * DMODEL]; Ap1 = &g_x [(size_t)(bm + r1) * DMODEL]; }
    else if (MODE == 1){ Ap0 = &g_h [(size_t)(bm + r0) * DMODEL]; Ap1 = &g_h [(size_t)(bm + r1) * DMODEL]; }
    else if (MODE == 2){ Ap0 = &g_x [(size_t)g_atok[bm + r0] * DMODEL]; Ap1 = &g_x [(size_t)g_atok[bm + r1] * DMODEL]; }
    else               { Ap0 = &g_h1[(size_t)(bm + r0) * HFF];    Ap1 = &g_h1[(size_t)(bm + r1) * HFF]; }

    const float* Bp0 = Bmat + (size_t)kb0 * N + bn + cb;
    const float* Bp1 = Bmat + (size_t)kb1 * N + bn + cb;

    float acc[2][8][4];
#pragma unroll
    for (int mt = 0; mt < 2; mt++)
#pragma unroll
        for (int nt = 0; nt < 8; nt++)
#pragma unroll
            for (int i = 0; i < 4; i++) acc[mt][nt][i] = 0.f;

    float4 pa0 = *(const float4*)(Ap0 + k4);
    float4 pa1 = *(const float4*)(Ap1 + k4);
    float4 pb0 = *(const float4*)Bp0;
    float4 pb1 = *(const float4*)Bp1;

    // stage buffer 0
    {
        *(uint2*)&Ah[0][r0][k4] = make_uint2(hi2u(pa0.x,pa0.y), hi2u(pa0.z,pa0.w));
        *(uint2*)&Al[0][r0][k4] = make_uint2(lo2u(pa0.x,pa0.y), lo2u(pa0.z,pa0.w));
        *(uint2*)&Ah[0][r1][k4] = make_uint2(hi2u(pa1.x,pa1.y), hi2u(pa1.z,pa1.w));
        *(uint2*)&Al[0][r1][k4] = make_uint2(lo2u(pa1.x,pa1.y), lo2u(pa1.z,pa1.w));
        *(uint2*)&Bh[0][kb0][cb] = make_uint2(hi2u(pb0.x,pb0.y), hi2u(pb0.z,pb0.w));
        *(uint2*)&Bl[0][kb0][cb] = make_uint2(lo2u(pb0.x,pb0.y), lo2u(pb0.z,pb0.w));
        *(uint2*)&Bh[0][kb1][cb] = make_uint2(hi2u(pb1.x,pb1.y), hi2u(pb1.z,pb1.w));
        *(uint2*)&Bl[0][kb1][cb] = make_uint2(lo2u(pb1.x,pb1.y), lo2u(pb1.z,pb1.w));
    }
    __syncthreads();

    int arow = (lane & 15), akc = (lane >> 4) * 8;
    int bkr  = (lane & 7) + ((lane >> 3) & 1) * 8;
    int bnc  = wn * 64 + (lane >> 4) * 8;

    int buf = 0;
    for (int k0 = 0; k0 < K; k0 += 16){
        bool more = (k0 + 16 < K);
        if (more){
            pa0 = *(const float4*)(Ap0 + k0 + 16 + k4);
            pa1 = *(const float4*)(Ap1 + k0 + 16 + k4);
            pb0 = *(const float4*)(Bp0 + (size_t)16 * N);
            pb1 = *(const float4*)(Bp1 + (size_t)16 * N);
            Bp0 += (size_t)16 * N; Bp1 += (size_t)16 * N;
        }

        // ---- fragments + MMA on current buffer ----
        unsigned ah[2][4], al[2][4];
#pragma unroll
        for (int mt = 0; mt < 2; mt++){
            int r = wm*32 + mt*16 + arow;
            ldsm4(ah[mt], &Ah[buf][r][akc]);
            ldsm4(al[mt], &Al[buf][r][akc]);
        }
#pragma unroll
        for (int ng = 0; ng < 4; ng++){
            unsigned bh[4], bl[4];
            ldsm4t(bh, &Bh[buf][bkr][bnc + ng*16]);
            ldsm4t(bl, &Bl[buf][bkr][bnc + ng*16]);
#pragma unroll
            for (int mt = 0; mt < 2; mt++){
                mma_bf16(acc[mt][2*ng  ], ah[mt], bh[0], bh[1]);
                mma_bf16(acc[mt][2*ng  ], ah[mt], bl[0], bl[1]);
                mma_bf16(acc[mt][2*ng  ], al[mt], bh[0], bh[1]);
                mma_bf16(acc[mt][2*ng+1], ah[mt], bh[2], bh[3]);
                mma_bf16(acc[mt][2*ng+1], ah[mt], bl[2], bl[3]);
                mma_bf16(acc[mt][2*ng+1], al[mt], bh[2], bh[3]);
            }
        }

        if (more){
            int nb = buf ^ 1;
            *(uint2*)&Ah[nb][r0][k4] = make_uint2(hi2u(pa0.x,pa0.y), hi2u(pa0.z,pa0.w));
            *(uint2*)&Al[nb][r0][k4] = make_uint2(lo2u(pa0.x,pa0.y), lo2u(pa0.z,pa0.w));
            *(uint2*)&Ah[nb][r1][k4] = make_uint2(hi2u(pa1.x,pa1.y), hi2u(pa1.z,pa1.w));
            *(uint2*)&Al[nb][r1][k4] = make_uint2(lo2u(pa1.x,pa1.y), lo2u(pa1.z,pa1.w));
            *(uint2*)&Bh[nb][kb0][cb] = make_uint2(hi2u(pb0.x,pb0.y), hi2u(pb0.z,pb0.w));
            *(uint2*)&Bl[nb][kb0][cb] = make_uint2(lo2u(pb0.x,pb0.y), lo2u(pb0.z,pb0.w));
            *(uint2*)&Bh[nb][kb1][cb] = make_uint2(hi2u(pb1.x,pb1.y), hi2u(pb1.z,pb1.w));
            *(uint2*)&Bl[nb][kb1][cb] = make_uint2(lo2u(pb1.x,pb1.y), lo2u(pb1.z,pb1.w));
        }
        __syncthreads();
        buf ^= 1;
    }

    // epilogue. fragment: c0=(r,c) c1=(r,c+1) c2=(r+8,c) c3=(r+8,c+1)
    int rql = lane >> 2, rqm = lane & 3;
    int c_lo = 2 * rqm;
#pragma unroll
    for (int mt = 0; mt < 2; mt++){
        int grA = bm + wm*32 + mt*16 + rql;
        int grB = grA + 8;
        if (MODE == 3){
            bool okA = grA < rowLimit, okB = grB < rowLimit;
            int   tokA = okA ? g_atok[grA] : 0;  float wA = okA ? g_aw[grA] : 0.f;
            int   tokB = okB ? g_atok[grB] : 0;  float wB = okB ? g_aw[grB] : 0.f;
#pragma unroll
            for (int nt = 0; nt < 8; nt++){
                int gc = bn + wn*64 + nt*8 + c_lo;
                float b0 = biasB[gc], b1 = biasB[gc+1];
                if (okA){
                    atomicAdd(&g_moe[(size_t)tokA*DMODEL + gc    ], wA*(acc[mt][nt][0] + b0));
                    atomicAdd(&g_moe[(size_t)tokA*DMODEL + gc + 1], wA*(acc[mt][nt][1] + b1));
                }
                if (okB){
                    atomicAdd(&g_moe[(size_t)tokB*DMODEL + gc    ], wB*(acc[mt][nt][2] + b0));
                    atomicAdd(&g_moe[(size_t)tokB*DMODEL + gc + 1], wB*(acc[mt][nt][3] + b1));
                }
            }
        } else {
#pragma unroll
            for (int nt = 0; nt < 8; nt++){
                int gc = bn + wn*64 + nt*8 + c_lo;
                float b0 = biasB[gc], b1 = biasB[gc+1];
                float v0 = acc[mt][nt][0] + b0, v1 = acc[mt][nt][1] + b1;
                float v2 = acc[mt][nt][2] + b0, v3 = acc[mt][nt][3] + b1;
                if (MODE == 0){
                    g_qkv[(size_t)grA*QKVD + gc] = v0; g_qkv[(size_t)grA*QKVD + gc+1] = v1;
                    g_qkv[(size_t)grB*QKVD + gc] = v2; g_qkv[(size_t)grB*QKVD + gc+1] = v3;
                } else if (MODE == 1){
                    g_tmp[(size_t)grA*DMODEL + gc] = v0; g_tmp[(size_t)grA*DMODEL + gc+1] = v1;
                    g_tmp[(size_t)grB*DMODEL + gc] = v2; g_tmp[(size_t)grB*DMODEL + gc+1] = v3;
                } else {
                    g_h1[(size_t)grA*HFF + gc]   = fmaxf(v0, 0.f);
                    g_h1[(size_t)grA*HFF + gc+1] = fmaxf(v1, 0.f);
                    g_h1[(size_t)grB*HFF + gc]   = fmaxf(v2, 0.f);
                    g_h1[(size_t)grB*HFF + gc+1] = fmaxf(v3, 0.f);
                }
            }
        }
    }
}

// ---------------- flash attention: 16 queries x 64-key tiles ----------------
__global__ void __launch_bounds__(256)
attn_kernel(const int* __restrict__ amask){
    int qt = blockIdx.x, h = blockIdx.y, b = blockIdx.z;
    int tid = threadIdx.x, warp = tid >> 5, lane = tid & 31;
    int qbase = qt * 16;

    __shared__ __align__(16) float Qs[16][68];
    __shared__ __align__(16) float Ks[64][68];
    __shared__ __align__(16) float Vs[64][68];
    __shared__ __align__(16) float Ps[8][2][68];

    {
        int q = tid >> 4, d4 = (tid & 15) * 4;
        const float* src = &g_qkv[(size_t)(b*TSEQ + qbase + q)*QKVD + h*DHEAD + d4];
        float4 v = *(const float4*)src;
        Qs[q][d4] = v.x*0.125f; Qs[q][d4+1] = v.y*0.125f;
        Qs[q][d4+2] = v.z*0.125f; Qs[q][d4+3] = v.w*0.125f;
    }

    int qg0 = qbase + warp*2, qg1 = qg0 + 1;
    float m0 = -3.0e38f, m1 = -3.0e38f;
    float l0 = 0.f, l1 = 0.f;
    float o00 = 0.f, o01 = 0.f, o10 = 0.f, o11 = 0.f;

    int ntiles = (qbase + 15) / 64 + 1;
    for (int tile = 0; tile < ntiles; tile++){
        int j0 = tile * 64;
        __syncthreads();
#pragma unroll
        for (int p = 0; p < 4; p++){
            int idx = tid + p*256;
            int row = idx >> 4, d4 = (idx & 15)*4;
            size_t base = (size_t)(b*TSEQ + j0 + row)*QKVD + h*DHEAD + d4;
            *(float4*)&Ks[row][d4] = *(const float4*)&g_qkv[base + DMODEL];
            *(float4*)&Vs[row][d4] = *(const float4*)&g_qkv[base + 2*DMODEL];
        }
        __syncthreads();

        float s00=0.f, s01=0.f, s10=0.f, s11=0.f;
#pragma unroll
        for (int d = 0; d < 64; d += 4){
            float4 ka = *(const float4*)&Ks[lane][d];
            float4 kb = *(const float4*)&Ks[lane+32][d];
            float4 qa = *(const float4*)&Qs[warp*2][d];
            float4 qb = *(const float4*)&Qs[warp*2+1][d];
            s00 += qa.x*ka.x + qa.y*ka.y + qa.z*ka.z + qa.w*ka.w;
            s01 += qa.x*kb.x + qa.y*kb.y + qa.z*kb.z + qa.w*kb.w;
            s10 += qb.x*ka.x + qb.y*ka.y + qb.z*ka.z + qb.w*ka.w;
            s11 += qb.x*kb.x + qb.y*kb.y + qb.z*kb.z + qb.w*kb.w;
        }
        int j1 = j0 + lane, j2 = j0 + lane + 32;
        int am1 = amask[b*TSEQ + j1], am2 = amask[b*TSEQ + j2];
        if (j1 > qg0 || !am1) s00 = -1e9f;
        if (j2 > qg0 || !am2) s01 = -1e9f;
        if (j1 > qg1 || !am1) s10 = -1e9f;
        if (j2 > qg1 || !am2) s11 = -1e9f;

        {
            float tm = warpRedMax(fmaxf(s00, s01));
            float mn = fmaxf(m0, tm);
            float sc = __expf(m0 - mn);
            float pA = __expf(s00 - mn), pB = __expf(s01 - mn);
            l0 = l0*sc + warpRedSum(pA + pB);
            o00 *= sc; o01 *= sc; m0 = mn;
            Ps[warp][0][lane] = pA; Ps[warp][0][lane+32] = pB;
        }
        {
            float tm = warpRedMax(fmaxf(s10, s11));
            float mn = fmaxf(m1, tm);
            float sc = __expf(m1 - mn);
            float pA = __expf(s10 - mn), pB = __expf(s11 - mn);
            l1 = l1*sc + warpRedSum(pA + pB);
            o10 *= sc; o11 *= sc; m1 = mn;
            Ps[warp][1][lane] = pA; Ps[warp][1][lane+32] = pB;
        }
        __syncwarp();

#pragma unroll 4
        for (int j = 0; j < 64; j += 4){
            float4 P0 = *(const float4*)&Ps[warp][0][j];
            float4 P1 = *(const float4*)&Ps[warp][1][j];
#pragma unroll
            for (int jj = 0; jj < 4; jj++){
                float p0 = (&P0.x)[jj], p1 = (&P1.x)[jj];
                float v0 = Vs[j+jj][lane], v1 = Vs[j+jj][lane+32];
                o00 += p0*v0; o01 += p0*v1;
                o10 += p1*v0; o11 += p1*v1;
            }
        }
    }

    float inv0 = 1.f / l0, inv1 = 1.f / l1;
    size_t n0 = (size_t)(b*TSEQ + qg0)*DMODEL + h*DHEAD;
    size_t n1 = (size_t)(b*TSEQ + qg1)*DMODEL + h*DHEAD;
    g_h[n0 + lane]      = o00 * inv0;
    g_h[n0 + lane + 32] = o01 * inv0;
    g_h[n1 + lane]      = o10 * inv1;
    g_h[n1 + lane + 32] = o11 * inv1;
}

// ---------------- residual add + LayerNorm ----------------
__global__ void add_ln_kernel(int which, const float* __restrict__ g,
                              const float* __restrict__ bta){
    int n = blockIdx.x, tid = threadIdx.x;
    __shared__ float red[32];
    const float* addsrc = which ? g_moe : g_tmp;
    float v[4];
    float s = 0.f;
#pragma unroll
    for (int i = 0; i < 4; i++){
        int d = tid + i*256;
        v[i] = g_x[(size_t)n*DMODEL + d] + addsrc[(size_t)n*DMODEL + d];
        s += v[i];
    }
    float mean = blockRedSum(s, red) * (1.f/DMODEL);
    float vs = 0.f;
#pragma unroll
    for (int i = 0; i < 4; i++){ float dd = v[i] - mean; vs += dd*dd; }
    float var = blockRedSum(vs, red) * (1.f/DMODEL);
    float r = rsqrtf(var + 1e-5f);
#pragma unroll
    for (int i = 0; i < 4; i++){
        int d = tid + i*256;
        g_x[(size_t)n*DMODEL + d] = (v[i] - mean)*r*g[d] + bta[d];
    }
}

// ---------------- router ----------------
__global__ void gate_kernel(const float* __restrict__ W, const float* __restrict__ bb){
    int n = blockIdx.x, tid = threadIdx.x;       // 128 threads
    __shared__ float sred[NEXP][128];
    float acc[NEXP];
#pragma unroll
    for (int e = 0; e < NEXP; e++) acc[e] = 0.f;
    const float* xr = &g_x[(size_t)n*DMODEL];
    for (int d = tid; d < DMODEL; d += 128){
        float xv = xr[d];
#pragma unroll
        for (int e = 0; e < NEXP; e++) acc[e] += xv * W[d*NEXP + e];
    }
#pragma unroll
    for (int e = 0; e < NEXP; e++) sred[e][tid] = acc[e];
    __syncthreads();
    for (int s = 64; s > 0; s >>= 1){
        if (tid < s){
#pragma unroll
            for (int e = 0; e < NEXP; e++) sred[e][tid] += sred[e][tid + s];
        }
        __syncthreads();
    }
    if (tid == 0){
        float lg[NEXP], mx = -3e38f;
#pragma unroll
        for (int e = 0; e < NEXP; e++){ lg[e] = sred[e][0] + bb[e]; mx = fmaxf(mx, lg[e]); }
        float s = 0.f, p[NEXP];
#pragma unroll
        for (int e = 0; e < NEXP; e++){ p[e] = __expf(lg[e] - mx); s += p[e]; }
        float invs = 1.f / s;
#pragma unroll
        for (int e = 0; e < NEXP; e++){ p[e] *= invs; g_probs[n*NEXP + e] = p[e]; }
        int i1 = 0;
#pragma unroll
        for (int e = 1; e < NEXP; e++) if (p[e] > p[i1]) i1 = e;
        int i2 = (i1 == 0) ? 1 : 0;
#pragma unroll
        for (int e = 0; e < NEXP; e++) if (e != i1 && p[e] > p[i2]) i2 = e;
        float sw = p[i1] + p[i2];
        g_tki[n*2]   = i1; g_tki[n*2+1] = i2;
        g_tkw[n*2]   = p[i1] / sw;
        g_tkw[n*2+1] = p[i2] / sw;
        atomicAdd(&g_counts[i1], 1);
        atomicAdd(&g_counts[i2], 1);
    }
}

// ---------------- per-layer reset ----------------
__global__ void reset_kernel(){
    int i = blockIdx.x * blockDim.x + threadIdx.x;
    if (i < N_TOK*DMODEL) g_moe[i] = 0.f;
    if (i < CAP){ g_atok[i] = 0; g_aw[i] = 0.f; }
    if (i < NEXP){ g_counts[i] = 0; g_cursor[i] = 0; }
}

__global__ void scan_kernel(){
    if (threadIdx.x == 0){
        int o = 0;
        for (int e = 0; e < NEXP; e++){
            g_off[e] = o;
            o += (g_counts[e] + 127) & ~127;
        }
        g_off[NEXP] = o;
    }
}

__global__ void scatter_kernel(){
    int n = blockIdx.x * blockDim.x + threadIdx.x;
    if (n >= N_TOK) return;
#pragma unroll
    for (int k = 0; k < 2; k++){
        int e = g_tki[n*2 + k];
        int pos = atomicAdd(&g_cursor[e], 1);
        int slot = g_off[e] + pos;
        g_atok[slot] = n;
        g_aw[slot]   = g_tkw[n*2 + k];
    }
}

// ---------------- load-balance loss ----------------
__global__ void lb_part_kernel(){
    int e = blockIdx.x, tid = threadIdx.x;
    __shared__ float red[32];
    float s = 0.f;
    for (int n = tid; n < N_TOK; n += 256) s += g_probs[n*NEXP + e];
    float tot = blockRedSum(s, red);
    if (tid == 0)
        g_Pc[e] = (float)NEXP * ((float)g_counts[e] / (float)N_TOK) * (tot / (float)N_TOK);
}
__global__ void lb_acc_kernel(){
    if (threadIdx.x == 0){
        float s = 0.f;
        for (int e = 0; e < NEXP; e++) s += g_Pc[e];
        g_lb += s;
    }
}
__global__ void init_kernel(){ g_lb = 0.f; }

// ---------------- output ----------------
__global__ void finalize_kernel(float* __restrict__ out, int out_size){
    int i = blockIdx.x * blockDim.x + threadIdx.x;
    if (i >= out_size) return;
    if (i < N_TOK*DMODEL) out[i] = g_x[i];
    else                  out[i] = g_lb;
}

// ---------------- host orchestration ----------------
extern "C" void kernel_launch(void* const* d_in, const int* in_sizes, int n_in,
                              void* d_out, int out_size)
{
    const int*   ids  = (const int*)  d_in[0];
    const int*   am   = (const int*)  d_in[1];
    const float* emb  = (const float*)d_in[2];
    const float* pos  = (const float*)d_in[3];
    const float* Wqkv = (const float*)d_in[4];
    const float* bqkv = (const float*)d_in[5];
    const float* Wo   = (const float*)d_in[6];
    const float* bo   = (const float*)d_in[7];
    const float* ln1g = (const float*)d_in[8];
    const float* ln1b = (const float*)d_in[9];
    const float* ln2g = (const float*)d_in[10];
    const float* ln2b = (const float*)d_in[11];
    const float* gW   = (const float*)d_in[12];
    const float* gb   = (const float*)d_in[13];
    const float* W1   = (const float*)d_in[14];
    const float* b1   = (const float*)d_in[15];
    const float* W2   = (const float*)d_in[16];
    const float* b2   = (const float*)d_in[17];

    init_kernel<<<1, 1>>>();
    embed_kernel<<<N_TOK, 256>>>(ids, emb, pos);

    for (int l = 0; l < NLAYER; l++){
        mma_gemm<0><<<dim3(QKVD/128, N_TOK/128), 256>>>(
            Wqkv + (size_t)l*DMODEL*QKVD, bqkv + (size_t)l*QKVD, QKVD, DMODEL);
        attn_kernel<<<dim3(TSEQ/16, NHEAD, BATCH), 256>>>(am);
        mma_gemm<1><<<dim3(DMODEL/128, N_TOK/128), 256>>>(
            Wo + (size_t)l*DMODEL*DMODEL, bo + (size_t)l*DMODEL, DMODEL, DMODEL);
        add_ln_kernel<<<N_TOK, 256>>>(0, ln1g + (size_t)l*DMODEL, ln1b + (size_t)l*DMODEL);

        reset_kernel<<<(N_TOK*DMODEL + 255)/256, 256>>>();
        gate_kernel<<<N_TOK, 128>>>(gW + (size_t)l*DMODEL*NEXP, gb + (size_t)l*NEXP);
        scan_kernel<<<1, 1>>>();
        scatter_kernel<<<(N_TOK + 255)/256, 256>>>();

        mma_gemm<2><<<dim3(HFF/128, CAP/128), 256>>>(
            W1 + (size_t)l*NEXP*DMODEL*HFF, b1 + (size_t)l*NEXP*HFF, HFF, DMODEL);
        mma_gemm<3><<<dim3(DMODEL/128, CAP/128), 256>>>(
            W2 + (size_t)l*NEXP*HFF*DMODEL, b2 + (size_t)l*NEXP*DMODEL, DMODEL, HFF);

        lb_part_kernel<<<NEXP, 256>>>();
        lb_acc_kernel<<<1, 1>>>();

        add_ln_kernel<<<N_TOK, 256>>>(1, ln2g + (size_t)l*DMODEL, ln2b + (size_t)l*DMODEL);
    }

    int total = out_size > N_TOK*DMODEL ? out_size : N_TOK*DMODEL;
    finalize_kernel<<<(total + 255)/256, 256>>>((float*)d_out, out_size);
}

// round 6
// speedup vs baseline: 3.6455x; 1.1998x over previous
#include <cuda_runtime.h>
#include <cuda_bf16.h>
#include <math.h>

#define N_TOK   8192
#define DMODEL  1024
#define QKVD    3072
#define NHEAD   16
#define DHEAD   64
#define NEXP    8
#define HFF     4096
#define TSEQ    1024
#define BATCH   8
#define NLAYER  2
#define CAP     17408   // 16384 assignments + 8*128 alignment pad

// ---------------- device scratch ----------------
__device__ float g_x[N_TOK*DMODEL];
__device__ float g_qkv[(size_t)N_TOK*QKVD];
__device__ float g_h[N_TOK*DMODEL];
__device__ float g_tmp[N_TOK*DMODEL];
__device__ float g_moe[N_TOK*DMODEL];
__device__ float g_h1[(size_t)CAP*HFF];
__device__ float g_probs[N_TOK*NEXP];
__device__ int   g_tki[N_TOK*2];
__device__ float g_tkw[N_TOK*2];
__device__ int   g_counts[NEXP];
__device__ int   g_cursor[NEXP];
__device__ int   g_off[NEXP+1];
__device__ int   g_atok[CAP];
__device__ float g_aw[CAP];
__device__ float g_Pc[NEXP];
__device__ float g_lb;

// ---------------- reductions ----------------
__device__ __forceinline__ float warpRedSum(float v){
#pragma unroll
    for (int o = 16; o; o >>= 1) v += __shfl_xor_sync(0xffffffffu, v, o);
    return v;
}
__device__ float blockRedSum(float v, float* red){
    int lane = threadIdx.x & 31, w = threadIdx.x >> 5, nw = blockDim.x >> 5;
    __syncthreads();
    v = warpRedSum(v);
    if (lane == 0) red[w] = v;
    __syncthreads();
    if (w == 0){
        float x = (lane < nw) ? red[lane] : 0.f;
        x = warpRedSum(x);
        if (lane == 0) red[0] = x;
    }
    __syncthreads();
    return red[0];
}

// ---------------- bf16 helpers ----------------
__device__ __forceinline__ unsigned hi2u(float a, float b){
    __nv_bfloat162 h(__float2bfloat16(a), __float2bfloat16(b));
    return *(unsigned*)&h;
}
__device__ __forceinline__ unsigned lo2u(float a, float b){
    float ha = __bfloat162float(__float2bfloat16(a));
    float hb = __bfloat162float(__float2bfloat16(b));
    __nv_bfloat162 l(__float2bfloat16(a - ha), __float2bfloat16(b - hb));
    return *(unsigned*)&l;
}
__device__ __forceinline__ void mma_bf16(float c[4], const unsigned a[4],
                                         unsigned b0, unsigned b1){
    asm volatile("mma.sync.aligned.m16n8k16.row.col.f32.bf16.bf16.f32 "
        "{%0,%1,%2,%3}, {%4,%5,%6,%7}, {%8,%9}, {%0,%1,%2,%3};"
        : "+f"(c[0]), "+f"(c[1]), "+f"(c[2]), "+f"(c[3])
        : "r"(a[0]), "r"(a[1]), "r"(a[2]), "r"(a[3]), "r"(b0), "r"(b1));
}
__device__ __forceinline__ void ldsm4(unsigned r[4], const __nv_bfloat16* p){
    unsigned addr = (unsigned)__cvta_generic_to_shared((void*)p);
    asm volatile("ldmatrix.sync.aligned.m8n8.x4.shared.b16 {%0,%1,%2,%3}, [%4];"
        : "=r"(r[0]), "=r"(r[1]), "=r"(r[2]), "=r"(r[3]) : "r"(addr));
}
__device__ __forceinline__ void ldsm4t(unsigned r[4], const __nv_bfloat16* p){
    unsigned addr = (unsigned)__cvta_generic_to_shared((void*)p);
    asm volatile("ldmatrix.sync.aligned.m8n8.x4.trans.shared.b16 {%0,%1,%2,%3}, [%4];"
        : "=r"(r[0]), "=r"(r[1]), "=r"(r[2]), "=r"(r[3]) : "r"(addr));
}

// ---------------- embedding + positional ----------------
__global__ void embed_kernel(const int* __restrict__ ids,
                             const float* __restrict__ emb,
                             const float* __restrict__ pos){
    int n = blockIdx.x, tid = threadIdx.x;
    int t = n & (TSEQ - 1);
    int id = ids[n];
#pragma unroll
    for (int i = 0; i < 4; i++){
        int d = tid + i * 256;
        g_x[(size_t)n*DMODEL + d] = emb[(size_t)id*DMODEL + d] + pos[(size_t)t*DMODEL + d];
    }
}

// ------- bf16x3 split-fp32 tensor-core GEMM, 128x128 tile, BK=16 -------
#define APAD 24
#define BPAD 136
template<int MODE>
__global__ void __launch_bounds__(256)
mma_gemm(const float* __restrict__ Bmat, const float* __restrict__ biasB,
         int N, int K)
{
    int bn = blockIdx.x * 128;
    int bm = blockIdx.y * 128;
    int tid  = threadIdx.x;
    int warp = tid >> 5, lane = tid & 31;
    int wm = warp >> 1, wn = warp & 1;

    int e = 0, rowLimit = 0;
    if (MODE == 2 || MODE == 3){
        if (bm >= g_off[NEXP]) return;
#pragma unroll
        for (int i = 1; i < NEXP; i++) if (bm >= g_off[i]) e = i;
        rowLimit = g_off[e] + g_counts[e];
        Bmat  += (size_t)e * K * N;
        biasB += (size_t)e * N;
    }

    __shared__ __align__(16) __nv_bfloat16 Ah[2][128][APAD];
    __shared__ __align__(16) __nv_bfloat16 Al[2][128][APAD];
    __shared__ __align__(16) __nv_bfloat16 Bh[2][16][BPAD];
    __shared__ __align__(16) __nv_bfloat16 Bl[2][16][BPAD];

    int r0 = tid >> 2, r1 = r0 + 64;
    int k4 = (tid & 3) * 4;
    int kb0 = tid >> 5, kb1 = kb0 + 8;
    int cb  = (tid & 31) * 4;

    const float *Ap0, *Ap1;
    if      (MODE == 0){ Ap0 = &g_x [(size_t)(bm + r0) * DMODEL]; Ap1 = &g_x [(size_t)(bm + r1) * DMODEL]; }
    else if (MODE == 1){ Ap0 = &g_h [(size_t)(bm + r0) * DMODEL]; Ap1 = &g_h [(size_t)(bm + r1) * DMODEL]; }
    else if (MODE == 2){ Ap0 = &g_x [(size_t)g_atok[bm + r0] * DMODEL]; Ap1 = &g_x [(size_t)g_atok[bm + r1] * DMODEL]; }
    else               { Ap0 = &g_h1[(size_t)(bm + r0) * HFF];    Ap1 = &g_h1[(size_t)(bm + r1) * HFF]; }

    const float* Bp0 = Bmat + (size_t)kb0 * N + bn + cb;
    const float* Bp1 = Bmat + (size_t)kb1 * N + bn + cb;

    float acc[2][8][4];
#pragma unroll
    for (int mt = 0; mt < 2; mt++)
#pragma unroll
        for (int nt = 0; nt < 8; nt++)
#pragma unroll
            for (int i = 0; i < 4; i++) acc[mt][nt][i] = 0.f;

    float4 pa0 = *(const float4*)(Ap0 + k4);
    float4 pa1 = *(const float4*)(Ap1 + k4);
    float4 pb0 = *(const float4*)Bp0;
    float4 pb1 = *(const float4*)Bp1;

    {
        *(uint2*)&Ah[0][r0][k4] = make_uint2(hi2u(pa0.x,pa0.y), hi2u(pa0.z,pa0.w));
        *(uint2*)&Al[0][r0][k4] = make_uint2(lo2u(pa0.x,pa0.y), lo2u(pa0.z,pa0.w));
        *(uint2*)&Ah[0][r1][k4] = make_uint2(hi2u(pa1.x,pa1.y), hi2u(pa1.z,pa1.w));
        *(uint2*)&Al[0][r1][k4] = make_uint2(lo2u(pa1.x,pa1.y), lo2u(pa1.z,pa1.w));
        *(uint2*)&Bh[0][kb0][cb] = make_uint2(hi2u(pb0.x,pb0.y), hi2u(pb0.z,pb0.w));
        *(uint2*)&Bl[0][kb0][cb] = make_uint2(lo2u(pb0.x,pb0.y), lo2u(pb0.z,pb0.w));
        *(uint2*)&Bh[0][kb1][cb] = make_uint2(hi2u(pb1.x,pb1.y), hi2u(pb1.z,pb1.w));
        *(uint2*)&Bl[0][kb1][cb] = make_uint2(lo2u(pb1.x,pb1.y), lo2u(pb1.z,pb1.w));
    }
    __syncthreads();

    int arow = (lane & 15), akc = (lane >> 4) * 8;
    int bkr  = (lane & 7) + ((lane >> 3) & 1) * 8;
    int bnc  = wn * 64 + (lane >> 4) * 8;

    int buf = 0;
    for (int k0 = 0; k0 < K; k0 += 16){
        bool more = (k0 + 16 < K);
        if (more){
            pa0 = *(const float4*)(Ap0 + k0 + 16 + k4);
            pa1 = *(const float4*)(Ap1 + k0 + 16 + k4);
            pb0 = *(const float4*)(Bp0 + (size_t)16 * N);
            pb1 = *(const float4*)(Bp1 + (size_t)16 * N);
            Bp0 += (size_t)16 * N; Bp1 += (size_t)16 * N;
        }

        unsigned ah[2][4], al[2][4];
#pragma unroll
        for (int mt = 0; mt < 2; mt++){
            int r = wm*32 + mt*16 + arow;
            ldsm4(ah[mt], &Ah[buf][r][akc]);
            ldsm4(al[mt], &Al[buf][r][akc]);
        }
#pragma unroll
        for (int ng = 0; ng < 4; ng++){
            unsigned bh[4], bl[4];
            ldsm4t(bh, &Bh[buf][bkr][bnc + ng*16]);
            ldsm4t(bl, &Bl[buf][bkr][bnc + ng*16]);
#pragma unroll
            for (int mt = 0; mt < 2; mt++){
                mma_bf16(acc[mt][2*ng  ], ah[mt], bh[0], bh[1]);
                mma_bf16(acc[mt][2*ng  ], ah[mt], bl[0], bl[1]);
                mma_bf16(acc[mt][2*ng  ], al[mt], bh[0], bh[1]);
                mma_bf16(acc[mt][2*ng+1], ah[mt], bh[2], bh[3]);
                mma_bf16(acc[mt][2*ng+1], ah[mt], bl[2], bl[3]);
                mma_bf16(acc[mt][2*ng+1], al[mt], bh[2], bh[3]);
            }
        }

        if (more){
            int nb = buf ^ 1;
            *(uint2*)&Ah[nb][r0][k4] = make_uint2(hi2u(pa0.x,pa0.y), hi2u(pa0.z,pa0.w));
            *(uint2*)&Al[nb][r0][k4] = make_uint2(lo2u(pa0.x,pa0.y), lo2u(pa0.z,pa0.w));
            *(uint2*)&Ah[nb][r1][k4] = make_uint2(hi2u(pa1.x,pa1.y), hi2u(pa1.z,pa1.w));
            *(uint2*)&Al[nb][r1][k4] = make_uint2(lo2u(pa1.x,pa1.y), lo2u(pa1.z,pa1.w));
            *(uint2*)&Bh[nb][kb0][cb] = make_uint2(hi2u(pb0.x,pb0.y), hi2u(pb0.z,pb0.w));
            *(uint2*)&Bl[nb][kb0][cb] = make_uint2(lo2u(pb0.x,pb0.y), lo2u(pb0.z,pb0.w));
            *(uint2*)&Bh[nb][kb1][cb] = make_uint2(hi2u(pb1.x,pb1.y), hi2u(pb1.z,pb1.w));
            *(uint2*)&Bl[nb][kb1][cb] = make_uint2(lo2u(pb1.x,pb1.y), lo2u(pb1.z,pb1.w));
        }
        __syncthreads();
        buf ^= 1;
    }

    int rql = lane >> 2, rqm = lane & 3;
    int c_lo = 2 * rqm;
#pragma unroll
    for (int mt = 0; mt < 2; mt++){
        int grA = bm + wm*32 + mt*16 + rql;
        int grB = grA + 8;
        if (MODE == 3){
            bool okA = grA < rowLimit, okB = grB < rowLimit;
            int   tokA = okA ? g_atok[grA] : 0;  float wA = okA ? g_aw[grA] : 0.f;
            int   tokB = okB ? g_atok[grB] : 0;  float wB = okB ? g_aw[grB] : 0.f;
#pragma unroll
            for (int nt = 0; nt < 8; nt++){
                int gc = bn + wn*64 + nt*8 + c_lo;
                float b0 = biasB[gc], b1 = biasB[gc+1];
                if (okA){
                    atomicAdd(&g_moe[(size_t)tokA*DMODEL + gc    ], wA*(acc[mt][nt][0] + b0));
                    atomicAdd(&g_moe[(size_t)tokA*DMODEL + gc + 1], wA*(acc[mt][nt][1] + b1));
                }
                if (okB){
                    atomicAdd(&g_moe[(size_t)tokB*DMODEL + gc    ], wB*(acc[mt][nt][2] + b0));
                    atomicAdd(&g_moe[(size_t)tokB*DMODEL + gc + 1], wB*(acc[mt][nt][3] + b1));
                }
            }
        } else {
#pragma unroll
            for (int nt = 0; nt < 8; nt++){
                int gc = bn + wn*64 + nt*8 + c_lo;
                float b0 = biasB[gc], b1 = biasB[gc+1];
                float v0 = acc[mt][nt][0] + b0, v1 = acc[mt][nt][1] + b1;
                float v2 = acc[mt][nt][2] + b0, v3 = acc[mt][nt][3] + b1;
                if (MODE == 0){
                    g_qkv[(size_t)grA*QKVD + gc] = v0; g_qkv[(size_t)grA*QKVD + gc+1] = v1;
                    g_qkv[(size_t)grB*QKVD + gc] = v2; g_qkv[(size_t)grB*QKVD + gc+1] = v3;
                } else if (MODE == 1){
                    g_tmp[(size_t)grA*DMODEL + gc] = v0; g_tmp[(size_t)grA*DMODEL + gc+1] = v1;
                    g_tmp[(size_t)grB*DMODEL + gc] = v2; g_tmp[(size_t)grB*DMODEL + gc+1] = v3;
                } else {
                    g_h1[(size_t)grA*HFF + gc]   = fmaxf(v0, 0.f);
                    g_h1[(size_t)grA*HFF + gc+1] = fmaxf(v1, 0.f);
                    g_h1[(size_t)grB*HFF + gc]   = fmaxf(v2, 0.f);
                    g_h1[(size_t)grB*HFF + gc+1] = fmaxf(v3, 0.f);
                }
            }
        }
    }
}

// -------- tensor-core flash attention (bf16x3), 64q x 64k tiles --------
// grid (T/64, NHEAD, BATCH), 128 threads (4 warps x 16 queries)
__global__ void __launch_bounds__(128)
attn_mma_kernel(const int* __restrict__ amask){
    int qt = gridDim.x - 1 - blockIdx.x;   // big blocks first
    int h = blockIdx.y, b = blockIdx.z;
    int tid = threadIdx.x, warp = tid >> 5, lane = tid & 31;
    int g = lane >> 2, q = lane & 3;
    int qbase = qt * 64;

    __shared__ __align__(16) __nv_bfloat16 Kh[64][72], Kl[64][72];
    __shared__ __align__(16) __nv_bfloat16 Vh[64][72], Vl[64][72];
    __shared__ int AMs[64];

    // stage Q (scaled by 1/8) into Kh/Kl, then pull fragments
    {
        int row = tid >> 1, c0 = (tid & 1) * 32;
        const float* src = &g_qkv[(size_t)(b*TSEQ + qbase + row)*QKVD + h*DHEAD + c0];
#pragma unroll
        for (int i = 0; i < 8; i++){
            float4 v = *(const float4*)(src + i*4);
            v.x *= 0.125f; v.y *= 0.125f; v.z *= 0.125f; v.w *= 0.125f;
            *(uint2*)&Kh[row][c0 + i*4] = make_uint2(hi2u(v.x,v.y), hi2u(v.z,v.w));
            *(uint2*)&Kl[row][c0 + i*4] = make_uint2(lo2u(v.x,v.y), lo2u(v.z,v.w));
        }
    }
    __syncthreads();

    unsigned qhf[4][4], qlf[4][4];
    {
        int r = warp*16 + (lane & 15);
        int kc = (lane >> 4) * 8;
#pragma unroll
        for (int kk = 0; kk < 4; kk++){
            ldsm4(qhf[kk], &Kh[r][kk*16 + kc]);
            ldsm4(qlf[kk], &Kl[r][kk*16 + kc]);
        }
    }

    float o[8][4];
#pragma unroll
    for (int i = 0; i < 8; i++)
#pragma unroll
        for (int j = 0; j < 4; j++) o[i][j] = 0.f;
    float m0 = -3.0e38f, m1 = -3.0e38f, l0 = 0.f, l1 = 0.f;

    int row0 = qbase + warp*16 + g, row1 = row0 + 8;
    int nrow = lane & 15, nkc = (lane >> 4) * 8;
    int bkr  = (lane & 7) + ((lane >> 3) & 1) * 8;
    int bnc  = (lane >> 4) * 8;

    int ntiles = qt + 1;
    for (int tile = 0; tile < ntiles; tile++){
        int j0 = tile * 64;
        __syncthreads();   // protects Q frags (iter 0) / prev-tile smem reads
        {
            int row = tid >> 1, c0 = (tid & 1) * 32;
            size_t base = (size_t)(b*TSEQ + j0 + row)*QKVD + h*DHEAD + c0;
            const float* ksrc = &g_qkv[base + DMODEL];
            const float* vsrc = &g_qkv[base + 2*DMODEL];
#pragma unroll
            for (int i = 0; i < 8; i++){
                float4 v = *(const float4*)(ksrc + i*4);
                *(uint2*)&Kh[row][c0+i*4] = make_uint2(hi2u(v.x,v.y), hi2u(v.z,v.w));
                *(uint2*)&Kl[row][c0+i*4] = make_uint2(lo2u(v.x,v.y), lo2u(v.z,v.w));
                float4 w = *(const float4*)(vsrc + i*4);
                *(uint2*)&Vh[row][c0+i*4] = make_uint2(hi2u(w.x,w.y), hi2u(w.z,w.w));
                *(uint2*)&Vl[row][c0+i*4] = make_uint2(lo2u(w.x,w.y), lo2u(w.z,w.w));
            }
            if (tid < 64) AMs[tid] = amask[b*TSEQ + j0 + tid];
        }
        __syncthreads();

        // ---- scores S = Q K^T ----
        float st[8][4];
#pragma unroll
        for (int i = 0; i < 8; i++)
#pragma unroll
            for (int j = 0; j < 4; j++) st[i][j] = 0.f;
#pragma unroll
        for (int nt2 = 0; nt2 < 4; nt2++){
#pragma unroll
            for (int kk = 0; kk < 4; kk++){
                unsigned kh[4], kl[4];
                ldsm4(kh, &Kh[nt2*16 + nrow][kk*16 + nkc]);
                ldsm4(kl, &Kl[nt2*16 + nrow][kk*16 + nkc]);
                mma_bf16(st[2*nt2  ], qhf[kk], kh[0], kh[2]);
                mma_bf16(st[2*nt2  ], qhf[kk], kl[0], kl[2]);
                mma_bf16(st[2*nt2  ], qlf[kk], kh[0], kh[2]);
                mma_bf16(st[2*nt2+1], qhf[kk], kh[1], kh[3]);
                mma_bf16(st[2*nt2+1], qhf[kk], kl[1], kl[3]);
                mma_bf16(st[2*nt2+1], qlf[kk], kh[1], kh[3]);
            }
        }

        // ---- mask (causal + attention_mask) ----
#pragma unroll
        for (int nt = 0; nt < 8; nt++){
            int lc = nt*8 + 2*q;
            int c  = j0 + lc;
            int a0 = AMs[lc], a1 = AMs[lc+1];
            if (c   > row0 || !a0) st[nt][0] = -1e9f;
            if (c+1 > row0 || !a1) st[nt][1] = -1e9f;
            if (c   > row1 || !a0) st[nt][2] = -1e9f;
            if (c+1 > row1 || !a1) st[nt][3] = -1e9f;
        }

        // ---- online softmax (fragment registers, quad reductions) ----
        float mx0 = -3.0e38f, mx1 = -3.0e38f;
#pragma unroll
        for (int nt = 0; nt < 8; nt++){
            mx0 = fmaxf(mx0, fmaxf(st[nt][0], st[nt][1]));
            mx1 = fmaxf(mx1, fmaxf(st[nt][2], st[nt][3]));
        }
#pragma unroll
        for (int off = 1; off <= 2; off <<= 1){
            mx0 = fmaxf(mx0, __shfl_xor_sync(0xffffffffu, mx0, off));
            mx1 = fmaxf(mx1, __shfl_xor_sync(0xffffffffu, mx1, off));
        }
        float mn0 = fmaxf(m0, mx0), mn1 = fmaxf(m1, mx1);
        float sc0 = __expf(m0 - mn0), sc1 = __expf(m1 - mn1);
        float ls0 = 0.f, ls1 = 0.f;
#pragma unroll
        for (int nt = 0; nt < 8; nt++){
            st[nt][0] = __expf(st[nt][0] - mn0);
            st[nt][1] = __expf(st[nt][1] - mn0);
            st[nt][2] = __expf(st[nt][2] - mn1);
            st[nt][3] = __expf(st[nt][3] - mn1);
            ls0 += st[nt][0] + st[nt][1];
            ls1 += st[nt][2] + st[nt][3];
        }
#pragma unroll
        for (int off = 1; off <= 2; off <<= 1){
            ls0 += __shfl_xor_sync(0xffffffffu, ls0, off);
            ls1 += __shfl_xor_sync(0xffffffffu, ls1, off);
        }
        l0 = l0*sc0 + ls0;  l1 = l1*sc1 + ls1;
#pragma unroll
        for (int nt = 0; nt < 8; nt++){
            o[nt][0] *= sc0; o[nt][1] *= sc0;
            o[nt][2] *= sc1; o[nt][3] *= sc1;
        }
        m0 = mn0; m1 = mn1;

        // ---- O += P V ----
#pragma unroll
        for (int kk2 = 0; kk2 < 4; kk2++){
            unsigned ph[4], pl[4];
            ph[0] = hi2u(st[2*kk2  ][0], st[2*kk2  ][1]);
            ph[1] = hi2u(st[2*kk2  ][2], st[2*kk2  ][3]);
            ph[2] = hi2u(st[2*kk2+1][0], st[2*kk2+1][1]);
            ph[3] = hi2u(st[2*kk2+1][2], st[2*kk2+1][3]);
            pl[0] = lo2u(st[2*kk2  ][0], st[2*kk2  ][1]);
            pl[1] = lo2u(st[2*kk2  ][2], st[2*kk2  ][3]);
            pl[2] = lo2u(st[2*kk2+1][0], st[2*kk2+1][1]);
            pl[3] = lo2u(st[2*kk2+1][2], st[2*kk2+1][3]);
#pragma unroll
            for (int dt2 = 0; dt2 < 4; dt2++){
                unsigned vh[4], vl[4];
                ldsm4t(vh, &Vh[kk2*16 + bkr][dt2*16 + bnc]);
                ldsm4t(vl, &Vl[kk2*16 + bkr][dt2*16 + bnc]);
                mma_bf16(o[2*dt2  ], ph, vh[0], vh[1]);
                mma_bf16(o[2*dt2  ], ph, vl[0], vl[1]);
                mma_bf16(o[2*dt2  ], pl, vh[0], vh[1]);
                mma_bf16(o[2*dt2+1], ph, vh[2], vh[3]);
                mma_bf16(o[2*dt2+1], ph, vl[2], vl[3]);
                mma_bf16(o[2*dt2+1], pl, vh[2], vh[3]);
            }
        }
    }

    float inv0 = 1.f / l0, inv1 = 1.f / l1;
    size_t n0 = (size_t)(b*TSEQ + row0)*DMODEL + h*DHEAD;
    size_t n1 = (size_t)(b*TSEQ + row1)*DMODEL + h*DHEAD;
#pragma unroll
    for (int dt = 0; dt < 8; dt++){
        int c = dt*8 + 2*q;
        *(float2*)&g_h[n0 + c] = make_float2(o[dt][0]*inv0, o[dt][1]*inv0);
        *(float2*)&g_h[n1 + c] = make_float2(o[dt][2]*inv1, o[dt][3]*inv1);
    }
}

// ---------------- residual add + LayerNorm ----------------
__global__ void add_ln_kernel(int which, const float* __restrict__ g,
                              const float* __restrict__ bta){
    int n = blockIdx.x, tid = threadIdx.x;
    __shared__ float red[32];
    const float* addsrc = which ? g_moe : g_tmp;
    float v[4];
    float s = 0.f;
#pragma unroll
    for (int i = 0; i < 4; i++){
        int d = tid + i*256;
        v[i] = g_x[(size_t)n*DMODEL + d] + addsrc[(size_t)n*DMODEL + d];
        s += v[i];
    }
    float mean = blockRedSum(s, red) * (1.f/DMODEL);
    float vs = 0.f;
#pragma unroll
    for (int i = 0; i < 4; i++){ float dd = v[i] - mean; vs += dd*dd; }
    float var = blockRedSum(vs, red) * (1.f/DMODEL);
    float r = rsqrtf(var + 1e-5f);
#pragma unroll
    for (int i = 0; i < 4; i++){
        int d = tid + i*256;
        g_x[(size_t)n*DMODEL + d] = (v[i] - mean)*r*g[d] + bta[d];
    }
}

// ---------------- router ----------------
__global__ void gate_kernel(const float* __restrict__ W, const float* __restrict__ bb){
    int n = blockIdx.x, tid = threadIdx.x;       // 128 threads
    __shared__ float sred[NEXP][128];
    float acc[NEXP];
#pragma unroll
    for (int e = 0; e < NEXP; e++) acc[e] = 0.f;
    const float* xr = &g_x[(size_t)n*DMODEL];
    for (int d = tid; d < DMODEL; d += 128){
        float xv = xr[d];
#pragma unroll
        for (int e = 0; e < NEXP; e++) acc[e] += xv * W[d*NEXP + e];
    }
#pragma unroll
    for (int e = 0; e < NEXP; e++) sred[e][tid] = acc[e];
    __syncthreads();
    for (int s = 64; s > 0; s >>= 1){
        if (tid < s){
#pragma unroll
            for (int e = 0; e < NEXP; e++) sred[e][tid] += sred[e][tid + s];
        }
        __syncthreads();
    }
    if (tid == 0){
        float lg[NEXP], mx = -3e38f;
#pragma unroll
        for (int e = 0; e < NEXP; e++){ lg[e] = sred[e][0] + bb[e]; mx = fmaxf(mx, lg[e]); }
        float s = 0.f, p[NEXP];
#pragma unroll
        for (int e = 0; e < NEXP; e++){ p[e] = __expf(lg[e] - mx); s += p[e]; }
        float invs = 1.f / s;
#pragma unroll
        for (int e = 0; e < NEXP; e++){ p[e] *= invs; g_probs[n*NEXP + e] = p[e]; }
        int i1 = 0;
#pragma unroll
        for (int e = 1; e < NEXP; e++) if (p[e] > p[i1]) i1 = e;
        int i2 = (i1 == 0) ? 1 : 0;
#pragma unroll
        for (int e = 0; e < NEXP; e++) if (e != i1 && p[e] > p[i2]) i2 = e;
        float sw = p[i1] + p[i2];
        g_tki[n*2]   = i1; g_tki[n*2+1] = i2;
        g_tkw[n*2]   = p[i1] / sw;
        g_tkw[n*2+1] = p[i2] / sw;
        atomicAdd(&g_counts[i1], 1);
        atomicAdd(&g_counts[i2], 1);
    }
}

// ---------------- per-layer reset ----------------
__global__ void reset_kernel(){
    int i = blockIdx.x * blockDim.x + threadIdx.x;
    if (i < N_TOK*DMODEL) g_moe[i] = 0.f;
    if (i < CAP){ g_atok[i] = 0; g_aw[i] = 0.f; }
    if (i < NEXP){ g_counts[i] = 0; g_cursor[i] = 0; }
}

__global__ void scan_kernel(){
    if (threadIdx.x == 0){
        int o = 0;
        for (int e = 0; e < NEXP; e++){
            g_off[e] = o;
            o += (g_counts[e] + 127) & ~127;
        }
        g_off[NEXP] = o;
    }
}

__global__ void scatter_kernel(){
    int n = blockIdx.x * blockDim.x + threadIdx.x;
    if (n >= N_TOK) return;
#pragma unroll
    for (int k = 0; k < 2; k++){
        int e = g_tki[n*2 + k];
        int pos = atomicAdd(&g_cursor[e], 1);
        int slot = g_off[e] + pos;
        g_atok[slot] = n;
        g_aw[slot]   = g_tkw[n*2 + k];
    }
}

// ---------------- load-balance loss ----------------
__global__ void lb_part_kernel(){
    int e = blockIdx.x, tid = threadIdx.x;
    __shared__ float red[32];
    float s = 0.f;
    for (int n = tid; n < N_TOK; n += 256) s += g_probs[n*NEXP + e];
    float tot = blockRedSum(s, red);
    if (tid == 0)
        g_Pc[e] = (float)NEXP * ((float)g_counts[e] / (float)N_TOK) * (tot / (float)N_TOK);
}
__global__ void lb_acc_kernel(){
    if (threadIdx.x == 0){
        float s = 0.f;
        for (int e = 0; e < NEXP; e++) s += g_Pc[e];
        g_lb += s;
    }
}
__global__ void init_kernel(){ g_lb = 0.f; }

// ---------------- output ----------------
__global__ void finalize_kernel(float* __restrict__ out, int out_size){
    int i = blockIdx.x * blockDim.x + threadIdx.x;
    if (i >= out_size) return;
    if (i < N_TOK*DMODEL) out[i] = g_x[i];
    else                  out[i] = g_lb;
}

// ---------------- host orchestration ----------------
extern "C" void kernel_launch(void* const* d_in, const int* in_sizes, int n_in,
                              void* d_out, int out_size)
{
    const int*   ids  = (const int*)  d_in[0];
    const int*   am   = (const int*)  d_in[1];
    const float* emb  = (const float*)d_in[2];
    const float* pos  = (const float*)d_in[3];
    const float* Wqkv = (const float*)d_in[4];
    const float* bqkv = (const float*)d_in[5];
    const float* Wo   = (const float*)d_in[6];
    const float* bo   = (const float*)d_in[7];
    const float* ln1g = (const float*)d_in[8];
    const float* ln1b = (const float*)d_in[9];
    const float* ln2g = (const float*)d_in[10];
    const float* ln2b = (const float*)d_in[11];
    const float* gW   = (const float*)d_in[12];
    const float* gb   = (const float*)d_in[13];
    const float* W1   = (const float*)d_in[14];
    const float* b1   = (const float*)d_in[15];
    const float* W2   = (const float*)d_in[16];
    const float* b2   = (const float*)d_in[17];

    init_kernel<<<1, 1>>>();
    embed_kernel<<<N_TOK, 256>>>(ids, emb, pos);

    for (int l = 0; l < NLAYER; l++){
        mma_gemm<0><<<dim3(QKVD/128, N_TOK/128), 256>>>(
            Wqkv + (size_t)l*DMODEL*QKVD, bqkv + (size_t)l*QKVD, QKVD, DMODEL);
        attn_mma_kernel<<<dim3(TSEQ/64, NHEAD, BATCH), 128>>>(am);
        mma_gemm<1><<<dim3(DMODEL/128, N_TOK/128), 256>>>(
            Wo + (size_t)l*DMODEL*DMODEL, bo + (size_t)l*DMODEL, DMODEL, DMODEL);
        add_ln_kernel<<<N_TOK, 256>>>(0, ln1g + (size_t)l*DMODEL, ln1b + (size_t)l*DMODEL);

        reset_kernel<<<(N_TOK*DMODEL + 255)/256, 256>>>();
        gate_kernel<<<N_TOK, 128>>>(gW + (size_t)l*DMODEL*NEXP, gb + (size_t)l*NEXP);
        scan_kernel<<<1, 1>>>();
        scatter_kernel<<<(N_TOK + 255)/256, 256>>>();

        mma_gemm<2><<<dim3(HFF/128, CAP/128), 256>>>(
            W1 + (size_t)l*NEXP*DMODEL*HFF, b1 + (size_t)l*NEXP*HFF, HFF, DMODEL);
        mma_gemm<3><<<dim3(DMODEL/128, CAP/128), 256>>>(
            W2 + (size_t)l*NEXP*HFF*DMODEL, b2 + (size_t)l*NEXP*DMODEL, DMODEL, HFF);

        lb_part_kernel<<<NEXP, 256>>>();
        lb_acc_kernel<<<1, 1>>>();

        add_ln_kernel<<<N_TOK, 256>>>(1, ln2g + (size_t)l*DMODEL, ln2b + (size_t)l*DMODEL);
    }

    int total = out_size > N_TOK*DMODEL ? out_size : N_TOK*DMODEL;
    finalize_kernel<<<(total + 255)/256, 256>>>((float*)d_out, out_size);
}